// round 9
// baseline (speedup 1.0000x reference)
#include <cuda_runtime.h>
#include <math.h>

// Problem constants
#define EDIM   256
#define HEADS  8
#define NL     1600   // local nodes (40x40)
#define NG     100    // global nodes (10x10)
#define HW     1600
#define ML     (NL*2) // 3200 rows (node-major, batch interleaved)
#define MG     (NG*2) // 200 rows

// ---------------- scratch ----------------
__device__ float d_Gn   [MG * EDIM];
__device__ float d_Ln   [ML * EDIM];
__device__ float d_qkvg [MG * 768];
__device__ float d_qkvl [ML * 768];
__device__ float d_att  [ML * EDIM];
__device__ float d_attg [MG * EDIM];
__device__ float d_proj [ML * EDIM];
__device__ float d_projg[MG * EDIM];
__device__ float d_gout [MG * EDIM];
__device__ float d_lout [ML * EDIM];
__device__ float d_qc   [ML * EDIM];
__device__ float d_kvc  [MG * 512];
__device__ float d_catt [ML * EDIM];
__device__ float d_cprj [ML * EDIM];

// ---------------- helpers ----------------
__device__ __forceinline__ float tf32r(float x) {
    unsigned u;
    asm("cvt.rna.tf32.f32 %0, %1;" : "=r"(u) : "f"(x));
    return __uint_as_float(u);
}
__device__ __forceinline__ unsigned f2u(float x) { return __float_as_uint(x); }

__device__ __forceinline__ void mma_tf32(float c[4],
    unsigned a0, unsigned a1, unsigned a2, unsigned a3,
    unsigned b0, unsigned b1) {
    asm volatile(
        "mma.sync.aligned.m16n8k8.row.col.f32.tf32.tf32.f32 "
        "{%0,%1,%2,%3}, {%4,%5,%6,%7}, {%8,%9}, {%0,%1,%2,%3};"
        : "+f"(c[0]), "+f"(c[1]), "+f"(c[2]), "+f"(c[3])
        : "r"(a0), "r"(a1), "r"(a2), "r"(a3), "r"(b0), "r"(b1));
}

__device__ __forceinline__ void cp_async16(unsigned dst, const void* src, int src_bytes) {
    asm volatile("cp.async.ca.shared.global [%0], [%1], 16, %2;"
                 :: "r"(dst), "l"(src), "r"(src_bytes));
}
#define CP_COMMIT() asm volatile("cp.async.commit_group;")
#define CP_WAIT1()  asm volatile("cp.async.wait_group 1;")
#define CP_WAIT0()  asm volatile("cp.async.wait_group 0;")

__device__ __forceinline__ void split_hl(float v, unsigned& h, unsigned& l) {
    float hf = tf32r(v);
    h = f2u(hf);
    l = f2u(v - hf);
}

// ---------------- prep: pool (blocks 0..199) + transpose to nodes (200..1799) ----------------
__global__ void prep_kernel(const float* __restrict__ x, float* __restrict__ gn,
                            float* __restrict__ ln) {
    int blk = blockIdx.x;
    int c = threadIdx.x;
    if (blk < 200) {
        int p = blk >> 1, b = blk & 1;
        int pr = p / 10, pc = p % 10;
        const float* xb = x + ((size_t)b * EDIM + c) * HW;
        float s = 0.f;
#pragma unroll
        for (int dy = 0; dy < 4; dy++)
#pragma unroll
            for (int dx = 0; dx < 4; dx++)
                s += xb[(pr * 4 + dy) * 40 + pc * 4 + dx];
        gn[(size_t)blk * EDIM + c] = s * (1.0f / 16.0f);
    } else {
        int n = blk - 200;
#pragma unroll
        for (int b = 0; b < 2; b++)
            ln[(size_t)(n * 2 + b) * EDIM + c] = x[((size_t)b * EDIM + c) * HW + n];
    }
}

// ---------------- 3xTF32 tensor GEMM with cp.async double buffering ----------------
// C[M,N] = A[M,256] @ W[N,256]^T + bias[N]; 64x64 tile, 256 threads (8 warps).
// Raw fp32 staged via cp.async; hi/lo tf32 split at fragment-load time.
__device__ __forceinline__ void gemm_tc_body(const float* __restrict__ A, const float* __restrict__ Wm,
                                             const float* __restrict__ bias, float* __restrict__ C,
                                             int M, int N, int bm, int bn) {
    __shared__ __align__(16) float As[2][64][36];
    __shared__ __align__(16) float Bs[2][64][36];

    const int tid = threadIdx.x;
    const int w = tid >> 5, lane = tid & 31;
    const int r = lane >> 2, c = lane & 3;
    const int ms = (w & 3) * 16;     // m strip (16 rows)
    const int ns = (w >> 2) * 32;    // n half (4 subtiles of 8)

    // per-thread load coords (two tasks of 512 total)
    const int row0 = tid >> 3;              // 0..31
    const int row1 = row0 + 32;             // 32..63
    const int k4   = (tid & 7) * 4;

    const float* gA0 = A + (size_t)((bm + row0 < M) ? bm + row0 : 0) * 256 + k4;
    const float* gA1 = A + (size_t)((bm + row1 < M) ? bm + row1 : 0) * 256 + k4;
    const int szA0 = (bm + row0 < M) ? 16 : 0;
    const int szA1 = (bm + row1 < M) ? 16 : 0;
    const float* gB0 = Wm + (size_t)(bn + row0) * 256 + k4;
    const float* gB1 = Wm + (size_t)(bn + row1) * 256 + k4;

    float acc[4][4];
#pragma unroll
    for (int nn = 0; nn < 4; nn++)
#pragma unroll
        for (int q = 0; q < 4; q++) acc[nn][q] = 0.f;

    // issue first chunk
    {
        unsigned sa0 = (unsigned)__cvta_generic_to_shared(&As[0][row0][k4]);
        unsigned sa1 = (unsigned)__cvta_generic_to_shared(&As[0][row1][k4]);
        unsigned sb0 = (unsigned)__cvta_generic_to_shared(&Bs[0][row0][k4]);
        unsigned sb1 = (unsigned)__cvta_generic_to_shared(&Bs[0][row1][k4]);
        cp_async16(sa0, gA0, szA0);
        cp_async16(sa1, gA1, szA1);
        cp_async16(sb0, gB0, 16);
        cp_async16(sb1, gB1, 16);
        CP_COMMIT();
    }

#pragma unroll
    for (int it = 0; it < 8; it++) {
        const int p = it & 1;
        if (it < 7) {
            const int knext = (it + 1) * 32;
            unsigned sa0 = (unsigned)__cvta_generic_to_shared(&As[p ^ 1][row0][k4]);
            unsigned sa1 = (unsigned)__cvta_generic_to_shared(&As[p ^ 1][row1][k4]);
            unsigned sb0 = (unsigned)__cvta_generic_to_shared(&Bs[p ^ 1][row0][k4]);
            unsigned sb1 = (unsigned)__cvta_generic_to_shared(&Bs[p ^ 1][row1][k4]);
            cp_async16(sa0, gA0 + knext, szA0);
            cp_async16(sa1, gA1 + knext, szA1);
            cp_async16(sb0, gB0 + knext, 16);
            cp_async16(sb1, gB1 + knext, 16);
            CP_COMMIT();
            CP_WAIT1();
        } else {
            CP_WAIT0();
        }
        __syncthreads();

#pragma unroll
        for (int kk = 0; kk < 32; kk += 8) {
            unsigned ah0, al0, ah1, al1, ah2, al2, ah3, al3;
            split_hl(As[p][ms + r][kk + c],         ah0, al0);
            split_hl(As[p][ms + r + 8][kk + c],     ah1, al1);
            split_hl(As[p][ms + r][kk + c + 4],     ah2, al2);
            split_hl(As[p][ms + r + 8][kk + c + 4], ah3, al3);
#pragma unroll
            for (int nn = 0; nn < 4; nn++) {
                int n = ns + nn * 8 + r;
                unsigned bh0, bl0, bh1, bl1;
                split_hl(Bs[p][n][kk + c],     bh0, bl0);
                split_hl(Bs[p][n][kk + c + 4], bh1, bl1);
                mma_tf32(acc[nn], ah0, ah1, ah2, ah3, bh0, bh1);
                mma_tf32(acc[nn], al0, al1, al2, al3, bh0, bh1);
                mma_tf32(acc[nn], ah0, ah1, ah2, ah3, bl0, bl1);
            }
        }
        __syncthreads();
    }

    // epilogue: acc[nn] -> rows (ms+r, ms+r+8), cols (2c, 2c+1) of subtile nn
#pragma unroll
    for (int nn = 0; nn < 4; nn++) {
        int ncol = bn + ns + nn * 8 + 2 * c;
        float2 bb = *(const float2*)(bias + ncol);
        int row = bm + ms + r;
        if (row < M)
            *(float2*)(C + (size_t)row * N + ncol) = make_float2(acc[nn][0] + bb.x, acc[nn][1] + bb.y);
        if (row + 8 < M)
            *(float2*)(C + (size_t)(row + 8) * N + ncol) = make_float2(acc[nn][2] + bb.x, acc[nn][3] + bb.y);
    }
}

__global__ __launch_bounds__(256)
void gemm_bias_kernel(const float* __restrict__ A, const float* __restrict__ W,
                      const float* __restrict__ bias, float* __restrict__ C, int M, int N) {
    gemm_tc_body(A, W, bias, C, M, N, blockIdx.y * 64, blockIdx.x * 64);
}

// dual GEMM: y < ySplit -> set0, else set1 (blocks with bn >= N early-exit)
__global__ __launch_bounds__(256)
void gemm_dual_kernel(const float* A0, const float* W0, const float* B0, float* C0, int M0, int N0,
                      const float* A1, const float* W1, const float* B1, float* C1, int M1, int N1,
                      int ySplit) {
    const float* A; const float* Wm; const float* bias; float* C; int M, N, by;
    if ((int)blockIdx.y < ySplit) { A = A0; Wm = W0; bias = B0; C = C0; M = M0; N = N0; by = blockIdx.y; }
    else { A = A1; Wm = W1; bias = B1; C = C1; M = M1; N = N1; by = blockIdx.y - ySplit; }
    int bn = blockIdx.x * 64;
    if (bn >= N) return;
    gemm_tc_body(A, Wm, bias, C, M, N, by * 64, bn);
}

// ---------------- tf32 MMA GAT attention (with K/V register prefetch) ----------------
// a0[i,j] = sigmoid(scale*(q0_i.k0_j - q1_i.k1_j));  O0 = A0@V0 ; O1 = (1-A0)@V1 (masked)
__global__ __launch_bounds__(256)
void gat_attn_mma(const float* __restrict__ qkvL, float* __restrict__ outL,
                  const float* __restrict__ qkvG, float* __restrict__ outG) {
    extern __shared__ float sm[];
    float* Qs = sm;                    // [64][68]  Qcat row-major [i][ck]
    float* Ks = sm + 64 * 68;          // [64][68]  Kcat row-major [j][ck] (b=1 negated)
    float* Am = sm + 2 * 64 * 68;      // [64][68]  a0 [i][j]
    float* Vs = sm + 3 * 64 * 68;      // [64][76]  V [j][ck]

    const float* qkv; float* out; int N, i0;
    if (blockIdx.x < 25) { qkv = qkvL; out = outL; N = NL; i0 = blockIdx.x * 64; }
    else                 { qkv = qkvG; out = outG; N = NG; i0 = (blockIdx.x - 25) * 64; }
    const int hc = blockIdx.y * 32;
    const int tid = threadIdx.x;
    const int w = tid >> 5, lane = tid & 31;
    const int r = lane >> 2, c = lane & 3;
    const float scale = 0.17677669529663687f;  // 1/sqrt(32)

    // per-thread K/V load coords (4 tasks)
    const int ljj = tid & 63;                 // j row
    const int ldq = tid >> 6;                 // 0..3 -> extended by t*4
    // load Q tile (tf32-rounded)
#pragma unroll
    for (int t = 0; t < 4; t++) {
        int idx = tid + t * 256;
        int ii = idx & 63, dq = idx >> 6;
        int b = dq >> 3, d4 = (dq & 7) * 4;
        float4 v = make_float4(0.f, 0.f, 0.f, 0.f);
        if (i0 + ii < N) v = *(const float4*)(qkv + (size_t)((i0 + ii) * 2 + b) * 768 + hc + d4);
        float* dst = Qs + ii * 68 + b * 32 + d4;
        dst[0] = tf32r(v.x); dst[1] = tf32r(v.y); dst[2] = tf32r(v.z); dst[3] = tf32r(v.w);
    }

    const int ib = (w & 3) * 16;
    const int jb = (w >> 2) * 32;    // GEMM1 j half
    const int batch = w >> 2;        // GEMM2 batch / d half
    float o[4][4];
#pragma unroll
    for (int dn = 0; dn < 4; dn++)
#pragma unroll
        for (int q = 0; q < 4; q++) o[dn][q] = 0.f;

    // prefetch tile 0 into registers
    float4 pk[4], pv[4];
#pragma unroll
    for (int t = 0; t < 4; t++) {
        int dq = ldq + t * 4;               // 0..15
        int b = dq >> 3, d4 = (dq & 7) * 4;
        pk[t] = make_float4(0.f, 0.f, 0.f, 0.f);
        pv[t] = make_float4(0.f, 0.f, 0.f, 0.f);
        if (ljj < N) {
            const float* base = qkv + (size_t)(ljj * 2 + b) * 768 + hc;
            pk[t] = *(const float4*)(base + 256 + d4);
            pv[t] = *(const float4*)(base + 512 + d4);
        }
    }

    for (int j0 = 0; j0 < N; j0 += 64) {
        __syncthreads();   // prev-iter reads of Ks/Vs/Am done (also orders Q writes on iter 0)
        // store prefetched K (b=1 negated) and V tiles
#pragma unroll
        for (int t = 0; t < 4; t++) {
            int dq = ldq + t * 4;
            int b = dq >> 3, d4 = (dq & 7) * 4;
            float4 kv = pk[t], vv = pv[t];
            if (b) { kv.x = -kv.x; kv.y = -kv.y; kv.z = -kv.z; kv.w = -kv.w; }
            int ck = b * 32 + d4;
            float* dk = Ks + ljj * 68 + ck;
            dk[0] = tf32r(kv.x); dk[1] = tf32r(kv.y); dk[2] = tf32r(kv.z); dk[3] = tf32r(kv.w);
            float* dv = Vs + ljj * 76 + ck;
            dv[0] = tf32r(vv.x); dv[1] = tf32r(vv.y); dv[2] = tf32r(vv.z); dv[3] = tf32r(vv.w);
        }
        __syncthreads();

        // GEMM1: S[16i x 32j] per warp, K-dim = 64 (concat)
        float s[4][4];
#pragma unroll
        for (int jn = 0; jn < 4; jn++)
#pragma unroll
            for (int q = 0; q < 4; q++) s[jn][q] = 0.f;
#pragma unroll
        for (int kk = 0; kk < 64; kk += 8) {
            unsigned a0 = f2u(Qs[(ib + r) * 68 + kk + c]);
            unsigned a1 = f2u(Qs[(ib + r + 8) * 68 + kk + c]);
            unsigned a2 = f2u(Qs[(ib + r) * 68 + kk + 4 + c]);
            unsigned a3 = f2u(Qs[(ib + r + 8) * 68 + kk + 4 + c]);
#pragma unroll
            for (int jn = 0; jn < 4; jn++) {
                const float* kb = Ks + (jb + jn * 8 + r) * 68 + kk;
                mma_tf32(s[jn], a0, a1, a2, a3, f2u(kb[c]), f2u(kb[4 + c]));
            }
        }
        // sigmoid + validity mask -> Am (tf32)
#pragma unroll
        for (int jn = 0; jn < 4; jn++) {
            int jc = jb + jn * 8 + 2 * c;
            bool valid = (j0 + jc) < N;   // pair-uniform (N even)
            float a00 = valid ? 1.f / (1.f + __expf(-scale * s[jn][0])) : 0.f;
            float a01 = valid ? 1.f / (1.f + __expf(-scale * s[jn][1])) : 0.f;
            float a10 = valid ? 1.f / (1.f + __expf(-scale * s[jn][2])) : 0.f;
            float a11 = valid ? 1.f / (1.f + __expf(-scale * s[jn][3])) : 0.f;
            *(float2*)(Am + (ib + r) * 68 + jc)     = make_float2(tf32r(a00), tf32r(a01));
            *(float2*)(Am + (ib + r + 8) * 68 + jc) = make_float2(tf32r(a10), tf32r(a11));
        }
        __syncthreads();

        // prefetch next tile during GEMM2
        if (j0 + 64 < N) {
#pragma unroll
            for (int t = 0; t < 4; t++) {
                int dq = ldq + t * 4;
                int b = dq >> 3, d4 = (dq & 7) * 4;
                int jj = j0 + 64 + ljj;
                pk[t] = make_float4(0.f, 0.f, 0.f, 0.f);
                pv[t] = make_float4(0.f, 0.f, 0.f, 0.f);
                if (jj < N) {
                    const float* base = qkv + (size_t)(jj * 2 + b) * 768 + hc;
                    pk[t] = *(const float4*)(base + 256 + d4);
                    pv[t] = *(const float4*)(base + 512 + d4);
                }
            }
        }

        // GEMM2: O[16i x 32d] per warp; batch0 uses A, batch1 uses (1-A) masked
#pragma unroll
        for (int kk = 0; kk < 64; kk += 8) {
            float f0 = Am[(ib + r) * 68 + kk + c];
            float f1 = Am[(ib + r + 8) * 68 + kk + c];
            float f2 = Am[(ib + r) * 68 + kk + 4 + c];
            float f3 = Am[(ib + r + 8) * 68 + kk + 4 + c];
            if (batch) {
                bool v0 = (j0 + kk + c) < N;
                bool v1 = (j0 + kk + 4 + c) < N;
                f0 = v0 ? tf32r(1.f - f0) : 0.f;
                f1 = v0 ? tf32r(1.f - f1) : 0.f;
                f2 = v1 ? tf32r(1.f - f2) : 0.f;
                f3 = v1 ? tf32r(1.f - f3) : 0.f;
            }
            unsigned a0 = f2u(f0), a1 = f2u(f1), a2 = f2u(f2), a3 = f2u(f3);
#pragma unroll
            for (int dn = 0; dn < 4; dn++) {
                int d = batch * 32 + dn * 8 + r;
                mma_tf32(o[dn], a0, a1, a2, a3,
                         f2u(Vs[(kk + c) * 76 + d]), f2u(Vs[(kk + 4 + c) * 76 + d]));
            }
        }
    }

    // epilogue: write O strip
#pragma unroll
    for (int dn = 0; dn < 4; dn++) {
        int d = dn * 8 + 2 * c;
        int i = i0 + ib + r;
        if (i < N)
            *(float2*)(out + (size_t)(i * 2 + batch) * 256 + hc + d) = make_float2(o[dn][0], o[dn][1]);
        if (i + 8 < N)
            *(float2*)(out + (size_t)((i + 8) * 2 + batch) * 256 + hc + d) = make_float2(o[dn][2], o[dn][3]);
    }
}

// ---------------- residual add + LayerNorm, dual (local rows then global rows) ----------------
__global__ void add_ln_dual(const float* __restrict__ yL, const float* __restrict__ resL,
                            const float* __restrict__ yG, const float* __restrict__ resG,
                            const float* __restrict__ ln_g, const float* __restrict__ ln_b,
                            float* __restrict__ outL, float* __restrict__ outG) {
    int row = blockIdx.x;
    const float* y; const float* res; const float* g; const float* bt; float* out; int rr;
    if (row < ML) { y = yL; res = resL; g = ln_g + 256; bt = ln_b + 256; out = outL; rr = row; }
    else          { y = yG; res = resG; g = ln_g;       bt = ln_b;       out = outG; rr = row - ML; }
    int c = threadIdx.x;
    float v = y[(size_t)rr * 256 + c] + res[(size_t)rr * 256 + c];

    float s = v, s2 = v * v;
#pragma unroll
    for (int o = 16; o; o >>= 1) {
        s  += __shfl_xor_sync(0xffffffffu, s,  o);
        s2 += __shfl_xor_sync(0xffffffffu, s2, o);
    }
    __shared__ float ws[8], ws2[8];
    int w = c >> 5, l = c & 31;
    if (l == 0) { ws[w] = s; ws2[w] = s2; }
    __syncthreads();
    if (w == 0) {
        float a  = (l < 8) ? ws[l]  : 0.f;
        float a2 = (l < 8) ? ws2[l] : 0.f;
#pragma unroll
        for (int o = 4; o; o >>= 1) {
            a  += __shfl_xor_sync(0xffffffffu, a,  o);
            a2 += __shfl_xor_sync(0xffffffffu, a2, o);
        }
        if (l == 0) { ws[0] = a; ws2[0] = a2; }
    }
    __syncthreads();
    float mean = ws[0] * (1.f / 256.f);
    float var  = ws2[0] * (1.f / 256.f) - mean * mean;
    float rs = rsqrtf(var + 1e-5f);
    out[(size_t)rr * 256 + c] = (v - mean) * rs * g[c] + bt[c];
}

// ---------------- final: residual add + LN + transpose to [B,C,HW] ----------------
__global__ __launch_bounds__(512)
void add_ln_tr_kernel(const float* __restrict__ y, const float* __restrict__ res,
                      const float* __restrict__ g, const float* __restrict__ bt,
                      float* __restrict__ out) {
    __shared__ float smn[16][260];
    int w = threadIdx.x >> 5, lane = threadIdx.x & 31;
    int row = blockIdx.x * 16 + w;
    float v[8];
    float s = 0.f, s2 = 0.f;
#pragma unroll
    for (int q = 0; q < 8; q++) {
        float t = y[(size_t)row * 256 + q * 32 + lane] + res[(size_t)row * 256 + q * 32 + lane];
        v[q] = t; s += t; s2 += t * t;
    }
#pragma unroll
    for (int o = 16; o; o >>= 1) {
        s  += __shfl_xor_sync(0xffffffffu, s,  o);
        s2 += __shfl_xor_sync(0xffffffffu, s2, o);
    }
    float mean = s * (1.f / 256.f);
    float var  = s2 * (1.f / 256.f) - mean * mean;
    float rs = rsqrtf(var + 1e-5f);
#pragma unroll
    for (int q = 0; q < 8; q++) {
        int c = q * 32 + lane;
        smn[w][c] = (v[q] - mean) * rs * g[c] + bt[c];
    }
    __syncthreads();
    int n0 = blockIdx.x * 8;
    int p = threadIdx.x;
    int b = p >> 8, c = p & 255;
    float4 w0, w1;
    w0.x = smn[0 + b][c]; w0.y = smn[2 + b][c]; w0.z = smn[4 + b][c]; w0.w = smn[6 + b][c];
    w1.x = smn[8 + b][c]; w1.y = smn[10 + b][c]; w1.z = smn[12 + b][c]; w1.w = smn[14 + b][c];
    size_t off = ((size_t)b * 256 + c) * (size_t)HW + n0;
    *(float4*)(out + off)     = w0;
    *(float4*)(out + off + 4) = w1;
}

// ---------------- cross attention: Q[3200 rows], K/V from 100 distinct g_out rows ----------------
__global__ void cross_attn_kernel(const float* __restrict__ Q, const float* __restrict__ KV,
                                  float* __restrict__ out) {
    __shared__ float Kt[2][32][100];
    __shared__ float Vs[2][100][32];
    const int hc = blockIdx.y * 32;
    const int i0 = blockIdx.x * 100;
    const int tid = threadIdx.x;

    for (int idx = tid; idx < 2 * 32 * 100; idx += 256) {
        int j = idx % 100; int t = idx / 100; int d = t & 31; int b = t >> 5;
        Kt[b][d][j] = KV[(size_t)(j * 2 + b) * 512 + hc + d];
    }
    for (int idx = tid; idx < 2 * 100 * 32; idx += 256) {
        int d = idx & 31; int t = idx >> 5; int j = t % 100; int b = t / 100;
        Vs[b][j][d] = KV[(size_t)(j * 2 + b) * 512 + 256 + hc + d];
    }
    __syncthreads();

    const int w = tid >> 5, lane = tid & 31;
    const float scale = 0.17677669529663687f;

    for (int p = w; p < 200; p += 8) {
        int li = p >> 1, b = p & 1;
        int i = i0 + li;
        float q = Q[(size_t)(i * 2 + b) * 256 + hc + lane];
        float s0 = 0.f, s1 = 0.f, s2 = 0.f, s3 = 0.f;
#pragma unroll
        for (int d = 0; d < 32; d++) {
            float qd = __shfl_sync(0xffffffffu, q, d);
            s0 += qd * Kt[b][d][lane];
            s1 += qd * Kt[b][d][lane + 32];
            s2 += qd * Kt[b][d][lane + 64];
            if (lane < 4) s3 += qd * Kt[b][d][lane + 96];
        }
        s0 *= scale; s1 *= scale; s2 *= scale;
        s3 = (lane < 4) ? s3 * scale : -1e30f;
        float m = fmaxf(fmaxf(s0, s1), fmaxf(s2, s3));
#pragma unroll
        for (int o = 16; o; o >>= 1) m = fmaxf(m, __shfl_xor_sync(0xffffffffu, m, o));
        float e0 = __expf(s0 - m), e1 = __expf(s1 - m), e2 = __expf(s2 - m);
        float e3 = (lane < 4) ? __expf(s3 - m) : 0.f;
        float sum = e0 + e1 + e2 + e3;
#pragma unroll
        for (int o = 16; o; o >>= 1) sum += __shfl_xor_sync(0xffffffffu, sum, o);
        float inv = 1.0f / sum;
        float a0 = e0 * inv, a1 = e1 * inv, a2 = e2 * inv, a3 = e3 * inv;

        float oa = 0.f;
#pragma unroll
        for (int jj = 0; jj < 32; jj++) {
            float a = __shfl_sync(0xffffffffu, a0, jj);
            oa += a * Vs[b][jj][lane];
        }
#pragma unroll
        for (int jj = 0; jj < 32; jj++) {
            float a = __shfl_sync(0xffffffffu, a1, jj);
            oa += a * Vs[b][32 + jj][lane];
        }
#pragma unroll
        for (int jj = 0; jj < 32; jj++) {
            float a = __shfl_sync(0xffffffffu, a2, jj);
            oa += a * Vs[b][64 + jj][lane];
        }
#pragma unroll
        for (int jj = 0; jj < 4; jj++) {
            float a = __shfl_sync(0xffffffffu, a3, jj);
            oa += a * Vs[b][96 + jj][lane];
        }
        out[(size_t)(i * 2 + b) * 256 + hc + lane] = oa;
    }
}

// ---------------- launch ----------------
extern "C" void kernel_launch(void* const* d_in, const int* in_sizes, int n_in,
                              void* d_out, int out_size) {
    const float* x       = (const float*)d_in[0];
    const float* gat_W   = (const float*)d_in[1];   // [2][4][256][256]
    const float* gat_b   = (const float*)d_in[2];   // [2][4][256]
    // d_in[3] = gat_rel: edge bias constant along batch softmax axis -> cancels exactly
    const float* cross_W = (const float*)d_in[4];
    const float* cross_b = (const float*)d_in[5];
    const float* ln_g    = (const float*)d_in[6];
    const float* ln_b    = (const float*)d_in[7];
    float* out = (float*)d_out;

    float *Gn, *Ln, *qkvg, *qkvl, *att, *attg, *proj, *projg, *gout, *lout, *qc, *kvc, *catt, *cprj;
    cudaGetSymbolAddress((void**)&Gn,    d_Gn);
    cudaGetSymbolAddress((void**)&Ln,    d_Ln);
    cudaGetSymbolAddress((void**)&qkvg,  d_qkvg);
    cudaGetSymbolAddress((void**)&qkvl,  d_qkvl);
    cudaGetSymbolAddress((void**)&att,   d_att);
    cudaGetSymbolAddress((void**)&attg,  d_attg);
    cudaGetSymbolAddress((void**)&proj,  d_proj);
    cudaGetSymbolAddress((void**)&projg, d_projg);
    cudaGetSymbolAddress((void**)&gout,  d_gout);
    cudaGetSymbolAddress((void**)&lout,  d_lout);
    cudaGetSymbolAddress((void**)&qc,    d_qc);
    cudaGetSymbolAddress((void**)&kvc,   d_kvc);
    cudaGetSymbolAddress((void**)&catt,  d_catt);
    cudaGetSymbolAddress((void**)&cprj,  d_cprj);

    const int W2 = 256 * 256;
    const int ATTN_SMEM = (3 * 64 * 68 + 64 * 76) * 4;   // 71680 bytes
    cudaFuncSetAttribute(gat_attn_mma, cudaFuncAttributeMaxDynamicSharedMemorySize, ATTN_SMEM);

    // node construction (pool + transpose merged)
    prep_kernel<<<1800, 256>>>(x, Gn, Ln);

    // qkv projections (local + global merged), 3xTF32 tensor GEMM
    gemm_dual_kernel<<<dim3(12, 54), 256>>>(
        Ln, gat_W + 4 * W2, gat_b + 1024, qkvl, ML, 768,
        Gn, gat_W,          gat_b,        qkvg, MG, 768, 50);

    // GAT attention (tf32 MMA, local x<25 + global x>=25)
    gat_attn_mma<<<dim3(27, HEADS), 256, ATTN_SMEM>>>(qkvl, att, qkvg, attg);

    // out projections (merged)
    gemm_dual_kernel<<<dim3(4, 54), 256>>>(
        att,  gat_W + 7 * W2, gat_b + 1024 + 768, proj,  ML, 256,
        attg, gat_W + 3 * W2, gat_b + 768,        projg, MG, 256, 50);

    // add + LN (merged)
    add_ln_dual<<<ML + MG, 256>>>(proj, Ln, projg, Gn, ln_g, ln_b, lout, gout);

    // cross projections: Q (local) + KV (global, 100 distinct keys) merged
    gemm_dual_kernel<<<dim3(8, 54), 256>>>(
        lout, cross_W,      cross_b,       qc,  ML, 256,
        gout, cross_W + W2, cross_b + 256, kvc, MG, 512, 50);

    cross_attn_kernel<<<dim3(16, HEADS), 256>>>(qc, kvc, catt);
    gemm_bias_kernel<<<dim3(4, 50), 256>>>(catt, cross_W + 3 * W2, cross_b + 768, cprj, ML, 256);
    add_ln_tr_kernel<<<200, 512>>>(cprj, lout, ln_g + 512, ln_b + 512, out);
}

// round 10
// speedup vs baseline: 1.1173x; 1.1173x over previous
#include <cuda_runtime.h>
#include <math.h>

// Problem constants
#define EDIM   256
#define HEADS  8
#define NL     1600   // local nodes (40x40)
#define NG     100    // global nodes (10x10)
#define HW     1600
#define ML     (NL*2) // 3200 rows (node-major, batch interleaved)
#define MG     (NG*2) // 200 rows

// ---------------- scratch ----------------
__device__ float d_Gn   [MG * EDIM];
__device__ float d_Ln   [ML * EDIM];
__device__ float d_qkvg [MG * 768];
__device__ float d_qkvl [ML * 768];
__device__ float d_att  [ML * EDIM];
__device__ float d_attg [MG * EDIM];
__device__ float d_proj [ML * EDIM];
__device__ float d_projg[MG * EDIM];
__device__ float d_gout [MG * EDIM];
__device__ float d_lout [ML * EDIM];
__device__ float d_qc   [ML * EDIM];
__device__ float d_kvc  [MG * 512];
__device__ float d_catt [ML * EDIM];
__device__ float d_cprj [ML * EDIM];

// ---------------- helpers ----------------
__device__ __forceinline__ float tf32r(float x) {
    unsigned u;
    asm("cvt.rna.tf32.f32 %0, %1;" : "=r"(u) : "f"(x));
    return __uint_as_float(u);
}
__device__ __forceinline__ unsigned f2u(float x) { return __float_as_uint(x); }
__device__ __forceinline__ unsigned tf32u(float x) {
    unsigned u;
    asm("cvt.rna.tf32.f32 %0, %1;" : "=r"(u) : "f"(x));
    return u;
}

__device__ __forceinline__ void mma_tf32(float c[4],
    unsigned a0, unsigned a1, unsigned a2, unsigned a3,
    unsigned b0, unsigned b1) {
    asm volatile(
        "mma.sync.aligned.m16n8k8.row.col.f32.tf32.tf32.f32 "
        "{%0,%1,%2,%3}, {%4,%5,%6,%7}, {%8,%9}, {%0,%1,%2,%3};"
        : "+f"(c[0]), "+f"(c[1]), "+f"(c[2]), "+f"(c[3])
        : "r"(a0), "r"(a1), "r"(a2), "r"(a3), "r"(b0), "r"(b1));
}

__device__ __forceinline__ void cp_async16(unsigned dst, const void* src, int src_bytes) {
    asm volatile("cp.async.ca.shared.global [%0], [%1], 16, %2;"
                 :: "r"(dst), "l"(src), "r"(src_bytes));
}
#define CP_COMMIT() asm volatile("cp.async.commit_group;")
#define CP_WAIT1()  asm volatile("cp.async.wait_group 1;")
#define CP_WAIT0()  asm volatile("cp.async.wait_group 0;")

// ---------------- prep: pool (blocks 0..199) + coalesced transpose (200..999) ----------------
__global__ __launch_bounds__(256)
void prep_kernel(const float* __restrict__ x, float* __restrict__ gn,
                 float* __restrict__ ln) {
    __shared__ float smt[32][33];
    int blk = blockIdx.x;
    int tid = threadIdx.x;
    if (blk < 200) {
        int p = blk >> 1, b = blk & 1;
        int c = tid;
        int pr = p / 10, pc = p % 10;
        const float* xb = x + ((size_t)b * EDIM + c) * HW;
        float s = 0.f;
#pragma unroll
        for (int dy = 0; dy < 4; dy++)
#pragma unroll
            for (int dx = 0; dx < 4; dx++)
                s += xb[(pr * 4 + dy) * 40 + pc * 4 + dx];
        gn[(size_t)blk * EDIM + c] = s * (1.0f / 16.0f);
    } else {
        // 32n x 32c tile transpose: x[b][c][n] -> ln[(n*2+b)][c]
        int t = blk - 200;            // 0..799
        int b  = t & 1;
        int ct = (t >> 1) & 7;        // 8 c-tiles
        int nt = t >> 4;              // 50 n-tiles
        int c0 = ct * 32, n0 = nt * 32;
        int ni = tid & 31, ci8 = tid >> 5;
#pragma unroll
        for (int q = 0; q < 4; q++) {
            int ci = ci8 + q * 8;
            smt[ci][ni] = x[((size_t)(b * 256 + c0 + ci)) * HW + n0 + ni];
        }
        __syncthreads();
        int cc = tid & 31, ni8 = tid >> 5;
#pragma unroll
        for (int q = 0; q < 4; q++) {
            int ni2 = ni8 + q * 8;
            ln[((size_t)((n0 + ni2) * 2 + b)) * 256 + c0 + cc] = smt[cc][ni2];
        }
    }
}

// ---------------- tf32 tensor GEMM with cp.async double buffering ----------------
// C[M,N] = A[M,256] @ W[N,256]^T + bias[N]; 64x64 tile, 256 threads (8 warps).
// Plain tf32 (round-to-nearest at fragment load), fp32 accumulate.
__device__ __forceinline__ void gemm_tc_body(const float* __restrict__ A, const float* __restrict__ Wm,
                                             const float* __restrict__ bias, float* __restrict__ C,
                                             int M, int N, int bm, int bn) {
    __shared__ __align__(16) float As[2][64][36];
    __shared__ __align__(16) float Bs[2][64][36];

    const int tid = threadIdx.x;
    const int w = tid >> 5, lane = tid & 31;
    const int r = lane >> 2, c = lane & 3;
    const int ms = (w & 3) * 16;     // m strip (16 rows)
    const int ns = (w >> 2) * 32;    // n half (4 subtiles of 8)

    const int row0 = tid >> 3;              // 0..31
    const int row1 = row0 + 32;             // 32..63
    const int k4   = (tid & 7) * 4;

    const float* gA0 = A + (size_t)((bm + row0 < M) ? bm + row0 : 0) * 256 + k4;
    const float* gA1 = A + (size_t)((bm + row1 < M) ? bm + row1 : 0) * 256 + k4;
    const int szA0 = (bm + row0 < M) ? 16 : 0;
    const int szA1 = (bm + row1 < M) ? 16 : 0;
    const float* gB0 = Wm + (size_t)(bn + row0) * 256 + k4;
    const float* gB1 = Wm + (size_t)(bn + row1) * 256 + k4;

    float acc[4][4];
#pragma unroll
    for (int nn = 0; nn < 4; nn++)
#pragma unroll
        for (int q = 0; q < 4; q++) acc[nn][q] = 0.f;

    // issue first chunk
    {
        unsigned sa0 = (unsigned)__cvta_generic_to_shared(&As[0][row0][k4]);
        unsigned sa1 = (unsigned)__cvta_generic_to_shared(&As[0][row1][k4]);
        unsigned sb0 = (unsigned)__cvta_generic_to_shared(&Bs[0][row0][k4]);
        unsigned sb1 = (unsigned)__cvta_generic_to_shared(&Bs[0][row1][k4]);
        cp_async16(sa0, gA0, szA0);
        cp_async16(sa1, gA1, szA1);
        cp_async16(sb0, gB0, 16);
        cp_async16(sb1, gB1, 16);
        CP_COMMIT();
    }

#pragma unroll
    for (int it = 0; it < 8; it++) {
        const int p = it & 1;
        if (it < 7) {
            const int knext = (it + 1) * 32;
            unsigned sa0 = (unsigned)__cvta_generic_to_shared(&As[p ^ 1][row0][k4]);
            unsigned sa1 = (unsigned)__cvta_generic_to_shared(&As[p ^ 1][row1][k4]);
            unsigned sb0 = (unsigned)__cvta_generic_to_shared(&Bs[p ^ 1][row0][k4]);
            unsigned sb1 = (unsigned)__cvta_generic_to_shared(&Bs[p ^ 1][row1][k4]);
            cp_async16(sa0, gA0 + knext, szA0);
            cp_async16(sa1, gA1 + knext, szA1);
            cp_async16(sb0, gB0 + knext, 16);
            cp_async16(sb1, gB1 + knext, 16);
            CP_COMMIT();
            CP_WAIT1();
        } else {
            CP_WAIT0();
        }
        __syncthreads();

#pragma unroll
        for (int kk = 0; kk < 32; kk += 8) {
            unsigned a0 = tf32u(As[p][ms + r][kk + c]);
            unsigned a1 = tf32u(As[p][ms + r + 8][kk + c]);
            unsigned a2 = tf32u(As[p][ms + r][kk + c + 4]);
            unsigned a3 = tf32u(As[p][ms + r + 8][kk + c + 4]);
#pragma unroll
            for (int nn = 0; nn < 4; nn++) {
                int n = ns + nn * 8 + r;
                unsigned b0 = tf32u(Bs[p][n][kk + c]);
                unsigned b1 = tf32u(Bs[p][n][kk + c + 4]);
                mma_tf32(acc[nn], a0, a1, a2, a3, b0, b1);
            }
        }
        __syncthreads();
    }

    // epilogue
#pragma unroll
    for (int nn = 0; nn < 4; nn++) {
        int ncol = bn + ns + nn * 8 + 2 * c;
        float2 bb = *(const float2*)(bias + ncol);
        int row = bm + ms + r;
        if (row < M)
            *(float2*)(C + (size_t)row * N + ncol) = make_float2(acc[nn][0] + bb.x, acc[nn][1] + bb.y);
        if (row + 8 < M)
            *(float2*)(C + (size_t)(row + 8) * N + ncol) = make_float2(acc[nn][2] + bb.x, acc[nn][3] + bb.y);
    }
}

__global__ __launch_bounds__(256)
void gemm_bias_kernel(const float* __restrict__ A, const float* __restrict__ W,
                      const float* __restrict__ bias, float* __restrict__ C, int M, int N) {
    gemm_tc_body(A, W, bias, C, M, N, blockIdx.y * 64, blockIdx.x * 64);
}

// dual GEMM: y < ySplit -> set0, else set1 (blocks with bn >= N early-exit)
__global__ __launch_bounds__(256)
void gemm_dual_kernel(const float* A0, const float* W0, const float* B0, float* C0, int M0, int N0,
                      const float* A1, const float* W1, const float* B1, float* C1, int M1, int N1,
                      int ySplit) {
    const float* A; const float* Wm; const float* bias; float* C; int M, N, by;
    if ((int)blockIdx.y < ySplit) { A = A0; Wm = W0; bias = B0; C = C0; M = M0; N = N0; by = blockIdx.y; }
    else { A = A1; Wm = W1; bias = B1; C = C1; M = M1; N = N1; by = blockIdx.y - ySplit; }
    int bn = blockIdx.x * 64;
    if (bn >= N) return;
    gemm_tc_body(A, Wm, bias, C, M, N, by * 64, bn);
}

// ---------------- tf32 MMA GAT attention (with K/V register prefetch) ----------------
// a0[i,j] = sigmoid(scale*(q0_i.k0_j - q1_i.k1_j));  O0 = A0@V0 ; O1 = (1-A0)@V1 (masked)
__global__ __launch_bounds__(256)
void gat_attn_mma(const float* __restrict__ qkvL, float* __restrict__ outL,
                  const float* __restrict__ qkvG, float* __restrict__ outG) {
    extern __shared__ float sm[];
    float* Qs = sm;                    // [64][68]  Qcat row-major [i][ck]
    float* Ks = sm + 64 * 68;          // [64][68]  Kcat row-major [j][ck] (b=1 negated)
    float* Am = sm + 2 * 64 * 68;      // [64][68]  a0 [i][j]
    float* Vs = sm + 3 * 64 * 68;      // [64][76]  V [j][ck]

    const float* qkv; float* out; int N, i0;
    if (blockIdx.x < 25) { qkv = qkvL; out = outL; N = NL; i0 = blockIdx.x * 64; }
    else                 { qkv = qkvG; out = outG; N = NG; i0 = (blockIdx.x - 25) * 64; }
    const int hc = blockIdx.y * 32;
    const int tid = threadIdx.x;
    const int w = tid >> 5, lane = tid & 31;
    const int r = lane >> 2, c = lane & 3;
    const float scale = 0.17677669529663687f;  // 1/sqrt(32)

    const int ljj = tid & 63;                 // j row
    const int ldq = tid >> 6;                 // 0..3
    // load Q tile (tf32-rounded)
#pragma unroll
    for (int t = 0; t < 4; t++) {
        int idx = tid + t * 256;
        int ii = idx & 63, dq = idx >> 6;
        int b = dq >> 3, d4 = (dq & 7) * 4;
        float4 v = make_float4(0.f, 0.f, 0.f, 0.f);
        if (i0 + ii < N) v = *(const float4*)(qkv + (size_t)((i0 + ii) * 2 + b) * 768 + hc + d4);
        float* dst = Qs + ii * 68 + b * 32 + d4;
        dst[0] = tf32r(v.x); dst[1] = tf32r(v.y); dst[2] = tf32r(v.z); dst[3] = tf32r(v.w);
    }

    const int ib = (w & 3) * 16;
    const int jb = (w >> 2) * 32;    // GEMM1 j half
    const int batch = w >> 2;        // GEMM2 batch / d half
    float o[4][4];
#pragma unroll
    for (int dn = 0; dn < 4; dn++)
#pragma unroll
        for (int q = 0; q < 4; q++) o[dn][q] = 0.f;

    // prefetch tile 0 into registers
    float4 pk[4], pv[4];
#pragma unroll
    for (int t = 0; t < 4; t++) {
        int dq = ldq + t * 4;
        int b = dq >> 3, d4 = (dq & 7) * 4;
        pk[t] = make_float4(0.f, 0.f, 0.f, 0.f);
        pv[t] = make_float4(0.f, 0.f, 0.f, 0.f);
        if (ljj < N) {
            const float* base = qkv + (size_t)(ljj * 2 + b) * 768 + hc;
            pk[t] = *(const float4*)(base + 256 + d4);
            pv[t] = *(const float4*)(base + 512 + d4);
        }
    }

    for (int j0 = 0; j0 < N; j0 += 64) {
        __syncthreads();
#pragma unroll
        for (int t = 0; t < 4; t++) {
            int dq = ldq + t * 4;
            int b = dq >> 3, d4 = (dq & 7) * 4;
            float4 kv = pk[t], vv = pv[t];
            if (b) { kv.x = -kv.x; kv.y = -kv.y; kv.z = -kv.z; kv.w = -kv.w; }
            int ck = b * 32 + d4;
            float* dk = Ks + ljj * 68 + ck;
            dk[0] = tf32r(kv.x); dk[1] = tf32r(kv.y); dk[2] = tf32r(kv.z); dk[3] = tf32r(kv.w);
            float* dv = Vs + ljj * 76 + ck;
            dv[0] = tf32r(vv.x); dv[1] = tf32r(vv.y); dv[2] = tf32r(vv.z); dv[3] = tf32r(vv.w);
        }
        __syncthreads();

        // GEMM1: S[16i x 32j] per warp, K-dim = 64 (concat)
        float s[4][4];
#pragma unroll
        for (int jn = 0; jn < 4; jn++)
#pragma unroll
            for (int q = 0; q < 4; q++) s[jn][q] = 0.f;
#pragma unroll
        for (int kk = 0; kk < 64; kk += 8) {
            unsigned a0 = f2u(Qs[(ib + r) * 68 + kk + c]);
            unsigned a1 = f2u(Qs[(ib + r + 8) * 68 + kk + c]);
            unsigned a2 = f2u(Qs[(ib + r) * 68 + kk + 4 + c]);
            unsigned a3 = f2u(Qs[(ib + r + 8) * 68 + kk + 4 + c]);
#pragma unroll
            for (int jn = 0; jn < 4; jn++) {
                const float* kb = Ks + (jb + jn * 8 + r) * 68 + kk;
                mma_tf32(s[jn], a0, a1, a2, a3, f2u(kb[c]), f2u(kb[4 + c]));
            }
        }
        // sigmoid + validity mask -> Am (tf32)
#pragma unroll
        for (int jn = 0; jn < 4; jn++) {
            int jc = jb + jn * 8 + 2 * c;
            bool valid = (j0 + jc) < N;   // pair-uniform (N even)
            float a00 = valid ? 1.f / (1.f + __expf(-scale * s[jn][0])) : 0.f;
            float a01 = valid ? 1.f / (1.f + __expf(-scale * s[jn][1])) : 0.f;
            float a10 = valid ? 1.f / (1.f + __expf(-scale * s[jn][2])) : 0.f;
            float a11 = valid ? 1.f / (1.f + __expf(-scale * s[jn][3])) : 0.f;
            *(float2*)(Am + (ib + r) * 68 + jc)     = make_float2(tf32r(a00), tf32r(a01));
            *(float2*)(Am + (ib + r + 8) * 68 + jc) = make_float2(tf32r(a10), tf32r(a11));
        }
        __syncthreads();

        // prefetch next tile during GEMM2
        if (j0 + 64 < N) {
#pragma unroll
            for (int t = 0; t < 4; t++) {
                int dq = ldq + t * 4;
                int b = dq >> 3, d4 = (dq & 7) * 4;
                int jj = j0 + 64 + ljj;
                pk[t] = make_float4(0.f, 0.f, 0.f, 0.f);
                pv[t] = make_float4(0.f, 0.f, 0.f, 0.f);
                if (jj < N) {
                    const float* base = qkv + (size_t)(jj * 2 + b) * 768 + hc;
                    pk[t] = *(const float4*)(base + 256 + d4);
                    pv[t] = *(const float4*)(base + 512 + d4);
                }
            }
        }

        // GEMM2: O[16i x 32d] per warp; batch0 uses A, batch1 uses (1-A) masked
#pragma unroll
        for (int kk = 0; kk < 64; kk += 8) {
            float f0 = Am[(ib + r) * 68 + kk + c];
            float f1 = Am[(ib + r + 8) * 68 + kk + c];
            float f2 = Am[(ib + r) * 68 + kk + 4 + c];
            float f3 = Am[(ib + r + 8) * 68 + kk + 4 + c];
            if (batch) {
                bool v0 = (j0 + kk + c) < N;
                bool v1 = (j0 + kk + 4 + c) < N;
                f0 = v0 ? tf32r(1.f - f0) : 0.f;
                f1 = v0 ? tf32r(1.f - f1) : 0.f;
                f2 = v1 ? tf32r(1.f - f2) : 0.f;
                f3 = v1 ? tf32r(1.f - f3) : 0.f;
            }
            unsigned a0 = f2u(f0), a1 = f2u(f1), a2 = f2u(f2), a3 = f2u(f3);
#pragma unroll
            for (int dn = 0; dn < 4; dn++) {
                int d = batch * 32 + dn * 8 + r;
                mma_tf32(o[dn], a0, a1, a2, a3,
                         f2u(Vs[(kk + c) * 76 + d]), f2u(Vs[(kk + 4 + c) * 76 + d]));
            }
        }
    }

    // epilogue: write O strip
#pragma unroll
    for (int dn = 0; dn < 4; dn++) {
        int d = dn * 8 + 2 * c;
        int i = i0 + ib + r;
        if (i < N)
            *(float2*)(out + (size_t)(i * 2 + batch) * 256 + hc + d) = make_float2(o[dn][0], o[dn][1]);
        if (i + 8 < N)
            *(float2*)(out + (size_t)((i + 8) * 2 + batch) * 256 + hc + d) = make_float2(o[dn][2], o[dn][3]);
    }
}

// ---------------- residual add + LayerNorm, warp-per-row, dual ----------------
__global__ __launch_bounds__(256)
void add_ln_dual(const float* __restrict__ yL, const float* __restrict__ resL,
                 const float* __restrict__ yG, const float* __restrict__ resG,
                 const float* __restrict__ ln_g, const float* __restrict__ ln_b,
                 float* __restrict__ outL, float* __restrict__ outG) {
    int w = threadIdx.x >> 5, lane = threadIdx.x & 31;
    int row = blockIdx.x * 8 + w;
    const float* y; const float* res; const float* g; const float* bt; float* out; int rr;
    if (row < ML) { y = yL; res = resL; g = ln_g + 256; bt = ln_b + 256; out = outL; rr = row; }
    else if (row < ML + MG) { y = yG; res = resG; g = ln_g; bt = ln_b; out = outG; rr = row - ML; }
    else return;

    float v[8];
    float s = 0.f, s2 = 0.f;
#pragma unroll
    for (int q = 0; q < 8; q++) {
        int c = q * 32 + lane;
        float t = y[(size_t)rr * 256 + c] + res[(size_t)rr * 256 + c];
        v[q] = t; s += t; s2 += t * t;
    }
#pragma unroll
    for (int o = 16; o; o >>= 1) {
        s  += __shfl_xor_sync(0xffffffffu, s,  o);
        s2 += __shfl_xor_sync(0xffffffffu, s2, o);
    }
    float mean = s * (1.f / 256.f);
    float var  = s2 * (1.f / 256.f) - mean * mean;
    float rs = rsqrtf(var + 1e-5f);
#pragma unroll
    for (int q = 0; q < 8; q++) {
        int c = q * 32 + lane;
        out[(size_t)rr * 256 + c] = (v[q] - mean) * rs * g[c] + bt[c];
    }
}

// ---------------- final: residual add + LN + transpose to [B,C,HW] ----------------
__global__ __launch_bounds__(512)
void add_ln_tr_kernel(const float* __restrict__ y, const float* __restrict__ res,
                      const float* __restrict__ g, const float* __restrict__ bt,
                      float* __restrict__ out) {
    __shared__ float smn[16][260];
    int w = threadIdx.x >> 5, lane = threadIdx.x & 31;
    int row = blockIdx.x * 16 + w;
    float v[8];
    float s = 0.f, s2 = 0.f;
#pragma unroll
    for (int q = 0; q < 8; q++) {
        float t = y[(size_t)row * 256 + q * 32 + lane] + res[(size_t)row * 256 + q * 32 + lane];
        v[q] = t; s += t; s2 += t * t;
    }
#pragma unroll
    for (int o = 16; o; o >>= 1) {
        s  += __shfl_xor_sync(0xffffffffu, s,  o);
        s2 += __shfl_xor_sync(0xffffffffu, s2, o);
    }
    float mean = s * (1.f / 256.f);
    float var  = s2 * (1.f / 256.f) - mean * mean;
    float rs = rsqrtf(var + 1e-5f);
#pragma unroll
    for (int q = 0; q < 8; q++) {
        int c = q * 32 + lane;
        smn[w][c] = (v[q] - mean) * rs * g[c] + bt[c];
    }
    __syncthreads();
    int n0 = blockIdx.x * 8;
    int p = threadIdx.x;
    int b = p >> 8, c = p & 255;
    float4 w0, w1;
    w0.x = smn[0 + b][c]; w0.y = smn[2 + b][c]; w0.z = smn[4 + b][c]; w0.w = smn[6 + b][c];
    w1.x = smn[8 + b][c]; w1.y = smn[10 + b][c]; w1.z = smn[12 + b][c]; w1.w = smn[14 + b][c];
    size_t off = ((size_t)b * 256 + c) * (size_t)HW + n0;
    *(float4*)(out + off)     = w0;
    *(float4*)(out + off + 4) = w1;
}

// ---------------- cross attention: Q[3200 rows], K/V from 100 distinct g_out rows ----------------
__global__ void cross_attn_kernel(const float* __restrict__ Q, const float* __restrict__ KV,
                                  float* __restrict__ out) {
    __shared__ float Kt[2][32][100];
    __shared__ float Vs[2][100][32];
    const int hc = blockIdx.y * 32;
    const int i0 = blockIdx.x * 100;
    const int tid = threadIdx.x;

    for (int idx = tid; idx < 2 * 32 * 100; idx += 256) {
        int j = idx % 100; int t = idx / 100; int d = t & 31; int b = t >> 5;
        Kt[b][d][j] = KV[(size_t)(j * 2 + b) * 512 + hc + d];
    }
    for (int idx = tid; idx < 2 * 100 * 32; idx += 256) {
        int d = idx & 31; int t = idx >> 5; int j = t % 100; int b = t / 100;
        Vs[b][j][d] = KV[(size_t)(j * 2 + b) * 512 + 256 + hc + d];
    }
    __syncthreads();

    const int w = tid >> 5, lane = tid & 31;
    const float scale = 0.17677669529663687f;

    for (int p = w; p < 200; p += 8) {
        int li = p >> 1, b = p & 1;
        int i = i0 + li;
        float q = Q[(size_t)(i * 2 + b) * 256 + hc + lane];
        float s0 = 0.f, s1 = 0.f, s2 = 0.f, s3 = 0.f;
#pragma unroll
        for (int d = 0; d < 32; d++) {
            float qd = __shfl_sync(0xffffffffu, q, d);
            s0 += qd * Kt[b][d][lane];
            s1 += qd * Kt[b][d][lane + 32];
            s2 += qd * Kt[b][d][lane + 64];
            if (lane < 4) s3 += qd * Kt[b][d][lane + 96];
        }
        s0 *= scale; s1 *= scale; s2 *= scale;
        s3 = (lane < 4) ? s3 * scale : -1e30f;
        float m = fmaxf(fmaxf(s0, s1), fmaxf(s2, s3));
#pragma unroll
        for (int o = 16; o; o >>= 1) m = fmaxf(m, __shfl_xor_sync(0xffffffffu, m, o));
        float e0 = __expf(s0 - m), e1 = __expf(s1 - m), e2 = __expf(s2 - m);
        float e3 = (lane < 4) ? __expf(s3 - m) : 0.f;
        float sum = e0 + e1 + e2 + e3;
#pragma unroll
        for (int o = 16; o; o >>= 1) sum += __shfl_xor_sync(0xffffffffu, sum, o);
        float inv = 1.0f / sum;
        float a0 = e0 * inv, a1 = e1 * inv, a2 = e2 * inv, a3 = e3 * inv;

        float oa = 0.f;
#pragma unroll
        for (int jj = 0; jj < 32; jj++) {
            float a = __shfl_sync(0xffffffffu, a0, jj);
            oa += a * Vs[b][jj][lane];
        }
#pragma unroll
        for (int jj = 0; jj < 32; jj++) {
            float a = __shfl_sync(0xffffffffu, a1, jj);
            oa += a * Vs[b][32 + jj][lane];
        }
#pragma unroll
        for (int jj = 0; jj < 32; jj++) {
            float a = __shfl_sync(0xffffffffu, a2, jj);
            oa += a * Vs[b][64 + jj][lane];
        }
#pragma unroll
        for (int jj = 0; jj < 4; jj++) {
            float a = __shfl_sync(0xffffffffu, a3, jj);
            oa += a * Vs[b][96 + jj][lane];
        }
        out[(size_t)(i * 2 + b) * 256 + hc + lane] = oa;
    }
}

// ---------------- launch ----------------
extern "C" void kernel_launch(void* const* d_in, const int* in_sizes, int n_in,
                              void* d_out, int out_size) {
    const float* x       = (const float*)d_in[0];
    const float* gat_W   = (const float*)d_in[1];   // [2][4][256][256]
    const float* gat_b   = (const float*)d_in[2];   // [2][4][256]
    // d_in[3] = gat_rel: edge bias constant along batch softmax axis -> cancels exactly
    const float* cross_W = (const float*)d_in[4];
    const float* cross_b = (const float*)d_in[5];
    const float* ln_g    = (const float*)d_in[6];
    const float* ln_b    = (const float*)d_in[7];
    float* out = (float*)d_out;

    float *Gn, *Ln, *qkvg, *qkvl, *att, *attg, *proj, *projg, *gout, *lout, *qc, *kvc, *catt, *cprj;
    cudaGetSymbolAddress((void**)&Gn,    d_Gn);
    cudaGetSymbolAddress((void**)&Ln,    d_Ln);
    cudaGetSymbolAddress((void**)&qkvg,  d_qkvg);
    cudaGetSymbolAddress((void**)&qkvl,  d_qkvl);
    cudaGetSymbolAddress((void**)&att,   d_att);
    cudaGetSymbolAddress((void**)&attg,  d_attg);
    cudaGetSymbolAddress((void**)&proj,  d_proj);
    cudaGetSymbolAddress((void**)&projg, d_projg);
    cudaGetSymbolAddress((void**)&gout,  d_gout);
    cudaGetSymbolAddress((void**)&lout,  d_lout);
    cudaGetSymbolAddress((void**)&qc,    d_qc);
    cudaGetSymbolAddress((void**)&kvc,   d_kvc);
    cudaGetSymbolAddress((void**)&catt,  d_catt);
    cudaGetSymbolAddress((void**)&cprj,  d_cprj);

    const int W2 = 256 * 256;
    const int ATTN_SMEM = (3 * 64 * 68 + 64 * 76) * 4;   // 71680 bytes
    cudaFuncSetAttribute(gat_attn_mma, cudaFuncAttributeMaxDynamicSharedMemorySize, ATTN_SMEM);

    // node construction (pool + coalesced transpose)
    prep_kernel<<<1000, 256>>>(x, Gn, Ln);

    // qkv projections (local + global merged), tf32 tensor GEMM
    gemm_dual_kernel<<<dim3(12, 54), 256>>>(
        Ln, gat_W + 4 * W2, gat_b + 1024, qkvl, ML, 768,
        Gn, gat_W,          gat_b,        qkvg, MG, 768, 50);

    // GAT attention (tf32 MMA, local x<25 + global x>=25)
    gat_attn_mma<<<dim3(27, HEADS), 256, ATTN_SMEM>>>(qkvl, att, qkvg, attg);

    // out projections (merged)
    gemm_dual_kernel<<<dim3(4, 54), 256>>>(
        att,  gat_W + 7 * W2, gat_b + 1024 + 768, proj,  ML, 256,
        attg, gat_W + 3 * W2, gat_b + 768,        projg, MG, 256, 50);

    // add + LN (merged, warp-per-row)
    add_ln_dual<<<(ML + MG) / 8, 256>>>(proj, Ln, projg, Gn, ln_g, ln_b, lout, gout);

    // cross projections: Q (local) + KV (global, 100 distinct keys) merged
    gemm_dual_kernel<<<dim3(8, 54), 256>>>(
        lout, cross_W,      cross_b,       qc,  ML, 256,
        gout, cross_W + W2, cross_b + 256, kvc, MG, 512, 50);

    cross_attn_kernel<<<dim3(16, HEADS), 256>>>(qc, kvc, catt);
    gemm_bias_kernel<<<dim3(4, 50), 256>>>(catt, cross_W + 3 * W2, cross_b + 768, cprj, ML, 256);
    add_ln_tr_kernel<<<200, 512>>>(cprj, lout, ln_g + 512, ln_b + 512, out);
}

// round 13
// speedup vs baseline: 1.1186x; 1.0012x over previous
#include <cuda_runtime.h>
#include <math.h>

// Problem constants
#define EDIM   256
#define HEADS  8
#define NL     1600   // local nodes (40x40)
#define NG     100    // global nodes (10x10)
#define HW     1600
#define ML     (NL*2) // 3200 rows (node-major, batch interleaved)
#define MG     (NG*2) // 200 rows

// ---------------- scratch ----------------
__device__ float d_Gn   [MG * EDIM];
__device__ float d_Ln   [ML * EDIM];
__device__ float d_qkvg [MG * 768];
__device__ float d_qkvl [ML * 768];
__device__ float d_att  [ML * EDIM];
__device__ float d_attg [MG * EDIM];
__device__ float d_proj [ML * EDIM];
__device__ float d_projg[MG * EDIM];
__device__ float d_gout [MG * EDIM];
__device__ float d_lout [ML * EDIM];
__device__ float d_qc   [ML * EDIM];
__device__ float d_kvc  [MG * 512];
__device__ float d_catt [ML * EDIM];
__device__ float d_cprj [ML * EDIM];

// ---------------- helpers ----------------
__device__ __forceinline__ float tf32r(float x) {
    unsigned u;
    asm("cvt.rna.tf32.f32 %0, %1;" : "=r"(u) : "f"(x));
    return __uint_as_float(u);
}
__device__ __forceinline__ unsigned f2u(float x) { return __float_as_uint(x); }
__device__ __forceinline__ unsigned tf32u(float x) {
    unsigned u;
    asm("cvt.rna.tf32.f32 %0, %1;" : "=r"(u) : "f"(x));
    return u;
}

__device__ __forceinline__ void mma_tf32(float c[4],
    unsigned a0, unsigned a1, unsigned a2, unsigned a3,
    unsigned b0, unsigned b1) {
    asm volatile(
        "mma.sync.aligned.m16n8k8.row.col.f32.tf32.tf32.f32 "
        "{%0,%1,%2,%3}, {%4,%5,%6,%7}, {%8,%9}, {%0,%1,%2,%3};"
        : "+f"(c[0]), "+f"(c[1]), "+f"(c[2]), "+f"(c[3])
        : "r"(a0), "r"(a1), "r"(a2), "r"(a3), "r"(b0), "r"(b1));
}

__device__ __forceinline__ void cp_async16(unsigned dst, const void* src, int src_bytes) {
    asm volatile("cp.async.ca.shared.global [%0], [%1], 16, %2;"
                 :: "r"(dst), "l"(src), "r"(src_bytes));
}
#define CP_COMMIT() asm volatile("cp.async.commit_group;")
#define CP_WAIT1()  asm volatile("cp.async.wait_group 1;")
#define CP_WAIT0()  asm volatile("cp.async.wait_group 0;")

// ---------------- prep: pool (blocks 0..199) + coalesced transpose (200..999) ----------------
__global__ __launch_bounds__(256)
void prep_kernel(const float* __restrict__ x, float* __restrict__ gn,
                 float* __restrict__ ln) {
    __shared__ float smt[32][33];
    int blk = blockIdx.x;
    int tid = threadIdx.x;
    if (blk < 200) {
        int p = blk >> 1, b = blk & 1;
        int c = tid;
        int pr = p / 10, pc = p % 10;
        const float* xb = x + ((size_t)b * EDIM + c) * HW;
        float s = 0.f;
#pragma unroll
        for (int dy = 0; dy < 4; dy++)
#pragma unroll
            for (int dx = 0; dx < 4; dx++)
                s += xb[(pr * 4 + dy) * 40 + pc * 4 + dx];
        gn[(size_t)blk * EDIM + c] = s * (1.0f / 16.0f);
    } else {
        // 32n x 32c tile transpose: x[b][c][n] -> ln[(n*2+b)][c]
        int t = blk - 200;            // 0..799
        int b  = t & 1;
        int ct = (t >> 1) & 7;        // 8 c-tiles
        int nt = t >> 4;              // 50 n-tiles
        int c0 = ct * 32, n0 = nt * 32;
        int ni = tid & 31, ci8 = tid >> 5;
#pragma unroll
        for (int q = 0; q < 4; q++) {
            int ci = ci8 + q * 8;
            smt[ci][ni] = x[((size_t)(b * 256 + c0 + ci)) * HW + n0 + ni];
        }
        __syncthreads();
        int cc = tid & 31, ni8 = tid >> 5;
#pragma unroll
        for (int q = 0; q < 4; q++) {
            int ni2 = ni8 + q * 8;
            ln[((size_t)((n0 + ni2) * 2 + b)) * 256 + c0 + cc] = smt[cc][ni2];
        }
    }
}

// ---------------- tf32 tensor GEMM with cp.async double buffering ----------------
// C[M,N] = A[M,256] @ W[N,256]^T + bias[N]; 64x64 tile, 256 threads (8 warps).
// Plain tf32 (round-to-nearest at fragment load), fp32 accumulate.
__device__ __forceinline__ void gemm_tc_body(const float* __restrict__ A, const float* __restrict__ Wm,
                                             const float* __restrict__ bias, float* __restrict__ C,
                                             int M, int N, int bm, int bn) {
    __shared__ __align__(16) float As[2][64][36];
    __shared__ __align__(16) float Bs[2][64][36];

    const int tid = threadIdx.x;
    const int w = tid >> 5, lane = tid & 31;
    const int r = lane >> 2, c = lane & 3;
    const int ms = (w & 3) * 16;     // m strip (16 rows)
    const int ns = (w >> 2) * 32;    // n half (4 subtiles of 8)

    const int row0 = tid >> 3;              // 0..31
    const int row1 = row0 + 32;             // 32..63
    const int k4   = (tid & 7) * 4;

    const float* gA0 = A + (size_t)((bm + row0 < M) ? bm + row0 : 0) * 256 + k4;
    const float* gA1 = A + (size_t)((bm + row1 < M) ? bm + row1 : 0) * 256 + k4;
    const int szA0 = (bm + row0 < M) ? 16 : 0;
    const int szA1 = (bm + row1 < M) ? 16 : 0;
    const float* gB0 = Wm + (size_t)(bn + row0) * 256 + k4;
    const float* gB1 = Wm + (size_t)(bn + row1) * 256 + k4;

    float acc[4][4];
#pragma unroll
    for (int nn = 0; nn < 4; nn++)
#pragma unroll
        for (int q = 0; q < 4; q++) acc[nn][q] = 0.f;

    // issue first chunk
    {
        unsigned sa0 = (unsigned)__cvta_generic_to_shared(&As[0][row0][k4]);
        unsigned sa1 = (unsigned)__cvta_generic_to_shared(&As[0][row1][k4]);
        unsigned sb0 = (unsigned)__cvta_generic_to_shared(&Bs[0][row0][k4]);
        unsigned sb1 = (unsigned)__cvta_generic_to_shared(&Bs[0][row1][k4]);
        cp_async16(sa0, gA0, szA0);
        cp_async16(sa1, gA1, szA1);
        cp_async16(sb0, gB0, 16);
        cp_async16(sb1, gB1, 16);
        CP_COMMIT();
    }

#pragma unroll
    for (int it = 0; it < 8; it++) {
        const int p = it & 1;
        if (it < 7) {
            const int knext = (it + 1) * 32;
            unsigned sa0 = (unsigned)__cvta_generic_to_shared(&As[p ^ 1][row0][k4]);
            unsigned sa1 = (unsigned)__cvta_generic_to_shared(&As[p ^ 1][row1][k4]);
            unsigned sb0 = (unsigned)__cvta_generic_to_shared(&Bs[p ^ 1][row0][k4]);
            unsigned sb1 = (unsigned)__cvta_generic_to_shared(&Bs[p ^ 1][row1][k4]);
            cp_async16(sa0, gA0 + knext, szA0);
            cp_async16(sa1, gA1 + knext, szA1);
            cp_async16(sb0, gB0 + knext, 16);
            cp_async16(sb1, gB1 + knext, 16);
            CP_COMMIT();
            CP_WAIT1();
        } else {
            CP_WAIT0();
        }
        __syncthreads();

#pragma unroll
        for (int kk = 0; kk < 32; kk += 8) {
            unsigned a0 = tf32u(As[p][ms + r][kk + c]);
            unsigned a1 = tf32u(As[p][ms + r + 8][kk + c]);
            unsigned a2 = tf32u(As[p][ms + r][kk + c + 4]);
            unsigned a3 = tf32u(As[p][ms + r + 8][kk + c + 4]);
#pragma unroll
            for (int nn = 0; nn < 4; nn++) {
                int n = ns + nn * 8 + r;
                unsigned b0 = tf32u(Bs[p][n][kk + c]);
                unsigned b1 = tf32u(Bs[p][n][kk + c + 4]);
                mma_tf32(acc[nn], a0, a1, a2, a3, b0, b1);
            }
        }
        __syncthreads();
    }

    // epilogue
#pragma unroll
    for (int nn = 0; nn < 4; nn++) {
        int ncol = bn + ns + nn * 8 + 2 * c;
        float2 bb = *(const float2*)(bias + ncol);
        int row = bm + ms + r;
        if (row < M)
            *(float2*)(C + (size_t)row * N + ncol) = make_float2(acc[nn][0] + bb.x, acc[nn][1] + bb.y);
        if (row + 8 < M)
            *(float2*)(C + (size_t)(row + 8) * N + ncol) = make_float2(acc[nn][2] + bb.x, acc[nn][3] + bb.y);
    }
}

__global__ __launch_bounds__(256)
void gemm_bias_kernel(const float* __restrict__ A, const float* __restrict__ W,
                      const float* __restrict__ bias, float* __restrict__ C, int M, int N) {
    gemm_tc_body(A, W, bias, C, M, N, blockIdx.y * 64, blockIdx.x * 64);
}

// dual GEMM: y < ySplit -> set0, else set1 (blocks with bn >= N early-exit)
__global__ __launch_bounds__(256)
void gemm_dual_kernel(const float* A0, const float* W0, const float* B0, float* C0, int M0, int N0,
                      const float* A1, const float* W1, const float* B1, float* C1, int M1, int N1,
                      int ySplit) {
    const float* A; const float* Wm; const float* bias; float* C; int M, N, by;
    if ((int)blockIdx.y < ySplit) { A = A0; Wm = W0; bias = B0; C = C0; M = M0; N = N0; by = blockIdx.y; }
    else { A = A1; Wm = W1; bias = B1; C = C1; M = M1; N = N1; by = blockIdx.y - ySplit; }
    int bn = blockIdx.x * 64;
    if (bn >= N) return;
    gemm_tc_body(A, Wm, bias, C, M, N, by * 64, bn);
}

// ---------------- tf32 MMA GAT attention (with K/V register prefetch) ----------------
// a0[i,j] = sigmoid(scale*(q0_i.k0_j - q1_i.k1_j));  O0 = A0@V0 ; O1 = (1-A0)@V1 (masked)
__global__ __launch_bounds__(256)
void gat_attn_mma(const float* __restrict__ qkvL, float* __restrict__ outL,
                  const float* __restrict__ qkvG, float* __restrict__ outG) {
    extern __shared__ float sm[];
    float* Qs = sm;                    // [64][68]  Qcat row-major [i][ck]
    float* Ks = sm + 64 * 68;          // [64][68]  Kcat row-major [j][ck] (b=1 negated)
    float* Am = sm + 2 * 64 * 68;      // [64][68]  a0 [i][j]
    float* Vs = sm + 3 * 64 * 68;      // [64][76]  V [j][ck]

    const float* qkv; float* out; int N, i0;
    if (blockIdx.x < 25) { qkv = qkvL; out = outL; N = NL; i0 = blockIdx.x * 64; }
    else                 { qkv = qkvG; out = outG; N = NG; i0 = (blockIdx.x - 25) * 64; }
    const int hc = blockIdx.y * 32;
    const int tid = threadIdx.x;
    const int w = tid >> 5, lane = tid & 31;
    const int r = lane >> 2, c = lane & 3;
    const float scale = 0.17677669529663687f;  // 1/sqrt(32)

    const int ljj = tid & 63;                 // j row
    const int ldq = tid >> 6;                 // 0..3
    // load Q tile (tf32-rounded)
#pragma unroll
    for (int t = 0; t < 4; t++) {
        int idx = tid + t * 256;
        int ii = idx & 63, dq = idx >> 6;
        int b = dq >> 3, d4 = (dq & 7) * 4;
        float4 v = make_float4(0.f, 0.f, 0.f, 0.f);
        if (i0 + ii < N) v = *(const float4*)(qkv + (size_t)((i0 + ii) * 2 + b) * 768 + hc + d4);
        float* dst = Qs + ii * 68 + b * 32 + d4;
        dst[0] = tf32r(v.x); dst[1] = tf32r(v.y); dst[2] = tf32r(v.z); dst[3] = tf32r(v.w);
    }

    const int ib = (w & 3) * 16;
    const int jb = (w >> 2) * 32;    // GEMM1 j half
    const int batch = w >> 2;        // GEMM2 batch / d half
    float o[4][4];
#pragma unroll
    for (int dn = 0; dn < 4; dn++)
#pragma unroll
        for (int q = 0; q < 4; q++) o[dn][q] = 0.f;

    // prefetch tile 0 into registers
    float4 pk[4], pv[4];
#pragma unroll
    for (int t = 0; t < 4; t++) {
        int dq = ldq + t * 4;
        int b = dq >> 3, d4 = (dq & 7) * 4;
        pk[t] = make_float4(0.f, 0.f, 0.f, 0.f);
        pv[t] = make_float4(0.f, 0.f, 0.f, 0.f);
        if (ljj < N) {
            const float* base = qkv + (size_t)(ljj * 2 + b) * 768 + hc;
            pk[t] = *(const float4*)(base + 256 + d4);
            pv[t] = *(const float4*)(base + 512 + d4);
        }
    }

    for (int j0 = 0; j0 < N; j0 += 64) {
        __syncthreads();
#pragma unroll
        for (int t = 0; t < 4; t++) {
            int dq = ldq + t * 4;
            int b = dq >> 3, d4 = (dq & 7) * 4;
            float4 kv = pk[t], vv = pv[t];
            if (b) { kv.x = -kv.x; kv.y = -kv.y; kv.z = -kv.z; kv.w = -kv.w; }
            int ck = b * 32 + d4;
            float* dk = Ks + ljj * 68 + ck;
            dk[0] = tf32r(kv.x); dk[1] = tf32r(kv.y); dk[2] = tf32r(kv.z); dk[3] = tf32r(kv.w);
            float* dv = Vs + ljj * 76 + ck;
            dv[0] = tf32r(vv.x); dv[1] = tf32r(vv.y); dv[2] = tf32r(vv.z); dv[3] = tf32r(vv.w);
        }
        __syncthreads();

        // GEMM1: S[16i x 32j] per warp, K-dim = 64 (concat)
        float s[4][4];
#pragma unroll
        for (int jn = 0; jn < 4; jn++)
#pragma unroll
            for (int q = 0; q < 4; q++) s[jn][q] = 0.f;
#pragma unroll
        for (int kk = 0; kk < 64; kk += 8) {
            unsigned a0 = f2u(Qs[(ib + r) * 68 + kk + c]);
            unsigned a1 = f2u(Qs[(ib + r + 8) * 68 + kk + c]);
            unsigned a2 = f2u(Qs[(ib + r) * 68 + kk + 4 + c]);
            unsigned a3 = f2u(Qs[(ib + r + 8) * 68 + kk + 4 + c]);
#pragma unroll
            for (int jn = 0; jn < 4; jn++) {
                const float* kb = Ks + (jb + jn * 8 + r) * 68 + kk;
                mma_tf32(s[jn], a0, a1, a2, a3, f2u(kb[c]), f2u(kb[4 + c]));
            }
        }
        // sigmoid + validity mask -> Am (tf32)
#pragma unroll
        for (int jn = 0; jn < 4; jn++) {
            int jc = jb + jn * 8 + 2 * c;
            bool valid = (j0 + jc) < N;   // pair-uniform (N even)
            float a00 = valid ? 1.f / (1.f + __expf(-scale * s[jn][0])) : 0.f;
            float a01 = valid ? 1.f / (1.f + __expf(-scale * s[jn][1])) : 0.f;
            float a10 = valid ? 1.f / (1.f + __expf(-scale * s[jn][2])) : 0.f;
            float a11 = valid ? 1.f / (1.f + __expf(-scale * s[jn][3])) : 0.f;
            *(float2*)(Am + (ib + r) * 68 + jc)     = make_float2(tf32r(a00), tf32r(a01));
            *(float2*)(Am + (ib + r + 8) * 68 + jc) = make_float2(tf32r(a10), tf32r(a11));
        }
        __syncthreads();

        // prefetch next tile during GEMM2
        if (j0 + 64 < N) {
#pragma unroll
            for (int t = 0; t < 4; t++) {
                int dq = ldq + t * 4;
                int b = dq >> 3, d4 = (dq & 7) * 4;
                int jj = j0 + 64 + ljj;
                pk[t] = make_float4(0.f, 0.f, 0.f, 0.f);
                pv[t] = make_float4(0.f, 0.f, 0.f, 0.f);
                if (jj < N) {
                    const float* base = qkv + (size_t)(jj * 2 + b) * 768 + hc;
                    pk[t] = *(const float4*)(base + 256 + d4);
                    pv[t] = *(const float4*)(base + 512 + d4);
                }
            }
        }

        // GEMM2: O[16i x 32d] per warp; batch0 uses A, batch1 uses (1-A) masked
#pragma unroll
        for (int kk = 0; kk < 64; kk += 8) {
            float f0 = Am[(ib + r) * 68 + kk + c];
            float f1 = Am[(ib + r + 8) * 68 + kk + c];
            float f2 = Am[(ib + r) * 68 + kk + 4 + c];
            float f3 = Am[(ib + r + 8) * 68 + kk + 4 + c];
            if (batch) {
                bool v0 = (j0 + kk + c) < N;
                bool v1 = (j0 + kk + 4 + c) < N;
                f0 = v0 ? tf32r(1.f - f0) : 0.f;
                f1 = v0 ? tf32r(1.f - f1) : 0.f;
                f2 = v1 ? tf32r(1.f - f2) : 0.f;
                f3 = v1 ? tf32r(1.f - f3) : 0.f;
            }
            unsigned a0 = f2u(f0), a1 = f2u(f1), a2 = f2u(f2), a3 = f2u(f3);
#pragma unroll
            for (int dn = 0; dn < 4; dn++) {
                int d = batch * 32 + dn * 8 + r;
                mma_tf32(o[dn], a0, a1, a2, a3,
                         f2u(Vs[(kk + c) * 76 + d]), f2u(Vs[(kk + 4 + c) * 76 + d]));
            }
        }
    }

    // epilogue: write O strip
#pragma unroll
    for (int dn = 0; dn < 4; dn++) {
        int d = dn * 8 + 2 * c;
        int i = i0 + ib + r;
        if (i < N)
            *(float2*)(out + (size_t)(i * 2 + batch) * 256 + hc + d) = make_float2(o[dn][0], o[dn][1]);
        if (i + 8 < N)
            *(float2*)(out + (size_t)((i + 8) * 2 + batch) * 256 + hc + d) = make_float2(o[dn][2], o[dn][3]);
    }
}

// ---------------- residual add + LayerNorm, warp-per-row, dual ----------------
__global__ __launch_bounds__(256)
void add_ln_dual(const float* __restrict__ yL, const float* __restrict__ resL,
                 const float* __restrict__ yG, const float* __restrict__ resG,
                 const float* __restrict__ ln_g, const float* __restrict__ ln_b,
                 float* __restrict__ outL, float* __restrict__ outG) {
    int w = threadIdx.x >> 5, lane = threadIdx.x & 31;
    int row = blockIdx.x * 8 + w;
    const float* y; const float* res; const float* g; const float* bt; float* out; int rr;
    if (row < ML) { y = yL; res = resL; g = ln_g + 256; bt = ln_b + 256; out = outL; rr = row; }
    else if (row < ML + MG) { y = yG; res = resG; g = ln_g; bt = ln_b; out = outG; rr = row - ML; }
    else return;

    float v[8];
    float s = 0.f, s2 = 0.f;
#pragma unroll
    for (int q = 0; q < 8; q++) {
        int c = q * 32 + lane;
        float t = y[(size_t)rr * 256 + c] + res[(size_t)rr * 256 + c];
        v[q] = t; s += t; s2 += t * t;
    }
#pragma unroll
    for (int o = 16; o; o >>= 1) {
        s  += __shfl_xor_sync(0xffffffffu, s,  o);
        s2 += __shfl_xor_sync(0xffffffffu, s2, o);
    }
    float mean = s * (1.f / 256.f);
    float var  = s2 * (1.f / 256.f) - mean * mean;
    float rs = rsqrtf(var + 1e-5f);
#pragma unroll
    for (int q = 0; q < 8; q++) {
        int c = q * 32 + lane;
        out[(size_t)rr * 256 + c] = (v[q] - mean) * rs * g[c] + bt[c];
    }
}

// ---------------- final: residual add + LN + transpose to [B,C,HW] ----------------
__global__ __launch_bounds__(512)
void add_ln_tr_kernel(const float* __restrict__ y, const float* __restrict__ res,
                      const float* __restrict__ g, const float* __restrict__ bt,
                      float* __restrict__ out) {
    __shared__ float smn[16][260];
    int w = threadIdx.x >> 5, lane = threadIdx.x & 31;
    int row = blockIdx.x * 16 + w;
    float v[8];
    float s = 0.f, s2 = 0.f;
#pragma unroll
    for (int q = 0; q < 8; q++) {
        float t = y[(size_t)row * 256 + q * 32 + lane] + res[(size_t)row * 256 + q * 32 + lane];
        v[q] = t; s += t; s2 += t * t;
    }
#pragma unroll
    for (int o = 16; o; o >>= 1) {
        s  += __shfl_xor_sync(0xffffffffu, s,  o);
        s2 += __shfl_xor_sync(0xffffffffu, s2, o);
    }
    float mean = s * (1.f / 256.f);
    float var  = s2 * (1.f / 256.f) - mean * mean;
    float rs = rsqrtf(var + 1e-5f);
#pragma unroll
    for (int q = 0; q < 8; q++) {
        int c = q * 32 + lane;
        smn[w][c] = (v[q] - mean) * rs * g[c] + bt[c];
    }
    __syncthreads();
    int n0 = blockIdx.x * 8;
    int p = threadIdx.x;
    int b = p >> 8, c = p & 255;
    float4 w0, w1;
    w0.x = smn[0 + b][c]; w0.y = smn[2 + b][c]; w0.z = smn[4 + b][c]; w0.w = smn[6 + b][c];
    w1.x = smn[8 + b][c]; w1.y = smn[10 + b][c]; w1.z = smn[12 + b][c]; w1.w = smn[14 + b][c];
    size_t off = ((size_t)b * 256 + c) * (size_t)HW + n0;
    *(float4*)(out + off)     = w0;
    *(float4*)(out + off + 4) = w1;
}

// ---------------- cross attention: Q[3200 rows], K/V from 100 distinct g_out rows ----------------
__global__ void cross_attn_kernel(const float* __restrict__ Q, const float* __restrict__ KV,
                                  float* __restrict__ out) {
    __shared__ float Kt[2][32][100];
    __shared__ float Vs[2][100][32];
    const int hc = blockIdx.y * 32;
    const int i0 = blockIdx.x * 100;
    const int tid = threadIdx.x;

    for (int idx = tid; idx < 2 * 32 * 100; idx += 256) {
        int j = idx % 100; int t = idx / 100; int d = t & 31; int b = t >> 5;
        Kt[b][d][j] = KV[(size_t)(j * 2 + b) * 512 + hc + d];
    }
    for (int idx = tid; idx < 2 * 100 * 32; idx += 256) {
        int d = idx & 31; int t = idx >> 5; int j = t % 100; int b = t / 100;
        Vs[b][j][d] = KV[(size_t)(j * 2 + b) * 512 + 256 + hc + d];
    }
    __syncthreads();

    const int w = tid >> 5, lane = tid & 31;
    const float scale = 0.17677669529663687f;

    for (int p = w; p < 200; p += 8) {
        int li = p >> 1, b = p & 1;
        int i = i0 + li;
        float q = Q[(size_t)(i * 2 + b) * 256 + hc + lane];
        float s0 = 0.f, s1 = 0.f, s2 = 0.f, s3 = 0.f;
#pragma unroll
        for (int d = 0; d < 32; d++) {
            float qd = __shfl_sync(0xffffffffu, q, d);
            s0 += qd * Kt[b][d][lane];
            s1 += qd * Kt[b][d][lane + 32];
            s2 += qd * Kt[b][d][lane + 64];
            if (lane < 4) s3 += qd * Kt[b][d][lane + 96];
        }
        s0 *= scale; s1 *= scale; s2 *= scale;
        s3 = (lane < 4) ? s3 * scale : -1e30f;
        float m = fmaxf(fmaxf(s0, s1), fmaxf(s2, s3));
#pragma unroll
        for (int o = 16; o; o >>= 1) m = fmaxf(m, __shfl_xor_sync(0xffffffffu, m, o));
        float e0 = __expf(s0 - m), e1 = __expf(s1 - m), e2 = __expf(s2 - m);
        float e3 = (lane < 4) ? __expf(s3 - m) : 0.f;
        float sum = e0 + e1 + e2 + e3;
#pragma unroll
        for (int o = 16; o; o >>= 1) sum += __shfl_xor_sync(0xffffffffu, sum, o);
        float inv = 1.0f / sum;
        float a0 = e0 * inv, a1 = e1 * inv, a2 = e2 * inv, a3 = e3 * inv;

        float oa = 0.f;
#pragma unroll
        for (int jj = 0; jj < 32; jj++) {
            float a = __shfl_sync(0xffffffffu, a0, jj);
            oa += a * Vs[b][jj][lane];
        }
#pragma unroll
        for (int jj = 0; jj < 32; jj++) {
            float a = __shfl_sync(0xffffffffu, a1, jj);
            oa += a * Vs[b][32 + jj][lane];
        }
#pragma unroll
        for (int jj = 0; jj < 32; jj++) {
            float a = __shfl_sync(0xffffffffu, a2, jj);
            oa += a * Vs[b][64 + jj][lane];
        }
#pragma unroll
        for (int jj = 0; jj < 4; jj++) {
            float a = __shfl_sync(0xffffffffu, a3, jj);
            oa += a * Vs[b][96 + jj][lane];
        }
        out[(size_t)(i * 2 + b) * 256 + hc + lane] = oa;
    }
}

// ---------------- launch ----------------
extern "C" void kernel_launch(void* const* d_in, const int* in_sizes, int n_in,
                              void* d_out, int out_size) {
    const float* x       = (const float*)d_in[0];
    const float* gat_W   = (const float*)d_in[1];   // [2][4][256][256]
    const float* gat_b   = (const float*)d_in[2];   // [2][4][256]
    // d_in[3] = gat_rel: edge bias constant along batch softmax axis -> cancels exactly
    const float* cross_W = (const float*)d_in[4];
    const float* cross_b = (const float*)d_in[5];
    const float* ln_g    = (const float*)d_in[6];
    const float* ln_b    = (const float*)d_in[7];
    float* out = (float*)d_out;

    float *Gn, *Ln, *qkvg, *qkvl, *att, *attg, *proj, *projg, *gout, *lout, *qc, *kvc, *catt, *cprj;
    cudaGetSymbolAddress((void**)&Gn,    d_Gn);
    cudaGetSymbolAddress((void**)&Ln,    d_Ln);
    cudaGetSymbolAddress((void**)&qkvg,  d_qkvg);
    cudaGetSymbolAddress((void**)&qkvl,  d_qkvl);
    cudaGetSymbolAddress((void**)&att,   d_att);
    cudaGetSymbolAddress((void**)&attg,  d_attg);
    cudaGetSymbolAddress((void**)&proj,  d_proj);
    cudaGetSymbolAddress((void**)&projg, d_projg);
    cudaGetSymbolAddress((void**)&gout,  d_gout);
    cudaGetSymbolAddress((void**)&lout,  d_lout);
    cudaGetSymbolAddress((void**)&qc,    d_qc);
    cudaGetSymbolAddress((void**)&kvc,   d_kvc);
    cudaGetSymbolAddress((void**)&catt,  d_catt);
    cudaGetSymbolAddress((void**)&cprj,  d_cprj);

    const int W2 = 256 * 256;
    const int ATTN_SMEM = (3 * 64 * 68 + 64 * 76) * 4;   // 71680 bytes
    cudaFuncSetAttribute(gat_attn_mma, cudaFuncAttributeMaxDynamicSharedMemorySize, ATTN_SMEM);

    // node construction (pool + coalesced transpose)
    prep_kernel<<<1000, 256>>>(x, Gn, Ln);

    // qkv projections (local + global merged), tf32 tensor GEMM
    gemm_dual_kernel<<<dim3(12, 54), 256>>>(
        Ln, gat_W + 4 * W2, gat_b + 1024, qkvl, ML, 768,
        Gn, gat_W,          gat_b,        qkvg, MG, 768, 50);

    // GAT attention (tf32 MMA, local x<25 + global x>=25)
    gat_attn_mma<<<dim3(27, HEADS), 256, ATTN_SMEM>>>(qkvl, att, qkvg, attg);

    // out projections (merged)
    gemm_dual_kernel<<<dim3(4, 54), 256>>>(
        att,  gat_W + 7 * W2, gat_b + 1024 + 768, proj,  ML, 256,
        attg, gat_W + 3 * W2, gat_b + 768,        projg, MG, 256, 50);

    // add + LN (merged, warp-per-row)
    add_ln_dual<<<(ML + MG) / 8, 256>>>(proj, Ln, projg, Gn, ln_g, ln_b, lout, gout);

    // cross projections: Q (local) + KV (global, 100 distinct keys) merged
    gemm_dual_kernel<<<dim3(8, 54), 256>>>(
        lout, cross_W,      cross_b,       qc,  ML, 256,
        gout, cross_W + W2, cross_b + 256, kvc, MG, 512, 50);

    cross_attn_kernel<<<dim3(16, HEADS), 256>>>(qc, kvc, catt);
    gemm_bias_kernel<<<dim3(4, 50), 256>>>(catt, cross_W + 3 * W2, cross_b + 768, cprj, ML, 256);
    add_ln_tr_kernel<<<200, 512>>>(cprj, lout, ln_g + 512, ln_b + 512, out);
}

// round 16
// speedup vs baseline: 1.1197x; 1.0010x over previous
#include <cuda_runtime.h>
#include <math.h>

// Problem constants
#define EDIM   256
#define HEADS  8
#define NL     1600   // local nodes (40x40)
#define NG     100    // global nodes (10x10)
#define HW     1600
#define ML     (NL*2) // 3200 rows (node-major, batch interleaved)
#define MG     (NG*2) // 200 rows

// ---------------- scratch ----------------
__device__ float d_Gn   [MG * EDIM];
__device__ float d_Ln   [ML * EDIM];
__device__ float d_qkvg [MG * 768];
__device__ float d_qkvl [ML * 768];
__device__ float d_att  [ML * EDIM];
__device__ float d_attg [MG * EDIM];
__device__ float d_proj [ML * EDIM];
__device__ float d_projg[MG * EDIM];
__device__ float d_gout [MG * EDIM];
__device__ float d_lout [ML * EDIM];
__device__ float d_qc   [ML * EDIM];
__device__ float d_kvc  [MG * 512];
__device__ float d_catt [ML * EDIM];
__device__ float d_cprj [ML * EDIM];

// ---------------- helpers ----------------
__device__ __forceinline__ float tf32r(float x) {
    unsigned u;
    asm("cvt.rna.tf32.f32 %0, %1;" : "=r"(u) : "f"(x));
    return __uint_as_float(u);
}
__device__ __forceinline__ unsigned f2u(float x) { return __float_as_uint(x); }
__device__ __forceinline__ unsigned tf32u(float x) {
    unsigned u;
    asm("cvt.rna.tf32.f32 %0, %1;" : "=r"(u) : "f"(x));
    return u;
}

__device__ __forceinline__ void mma_tf32(float c[4],
    unsigned a0, unsigned a1, unsigned a2, unsigned a3,
    unsigned b0, unsigned b1) {
    asm volatile(
        "mma.sync.aligned.m16n8k8.row.col.f32.tf32.tf32.f32 "
        "{%0,%1,%2,%3}, {%4,%5,%6,%7}, {%8,%9}, {%0,%1,%2,%3};"
        : "+f"(c[0]), "+f"(c[1]), "+f"(c[2]), "+f"(c[3])
        : "r"(a0), "r"(a1), "r"(a2), "r"(a3), "r"(b0), "r"(b1));
}

__device__ __forceinline__ void cp_async16(unsigned dst, const void* src, int src_bytes) {
    asm volatile("cp.async.ca.shared.global [%0], [%1], 16, %2;"
                 :: "r"(dst), "l"(src), "r"(src_bytes));
}
#define CP_COMMIT() asm volatile("cp.async.commit_group;")
#define CP_WAIT1()  asm volatile("cp.async.wait_group 1;")
#define CP_WAIT0()  asm volatile("cp.async.wait_group 0;")

// ---------------- prep: pool (blocks 0..199) + coalesced transpose (200..999) ----------------
__global__ __launch_bounds__(256)
void prep_kernel(const float* __restrict__ x, float* __restrict__ gn,
                 float* __restrict__ ln) {
    __shared__ float smt[32][33];
    int blk = blockIdx.x;
    int tid = threadIdx.x;
    if (blk < 200) {
        int p = blk >> 1, b = blk & 1;
        int c = tid;
        int pr = p / 10, pc = p % 10;
        const float* xb = x + ((size_t)b * EDIM + c) * HW;
        float s = 0.f;
#pragma unroll
        for (int dy = 0; dy < 4; dy++)
#pragma unroll
            for (int dx = 0; dx < 4; dx++)
                s += xb[(pr * 4 + dy) * 40 + pc * 4 + dx];
        gn[(size_t)blk * EDIM + c] = s * (1.0f / 16.0f);
    } else {
        // 32n x 32c tile transpose: x[b][c][n] -> ln[(n*2+b)][c]
        int t = blk - 200;            // 0..799
        int b  = t & 1;
        int ct = (t >> 1) & 7;        // 8 c-tiles
        int nt = t >> 4;              // 50 n-tiles
        int c0 = ct * 32, n0 = nt * 32;
        int ni = tid & 31, ci8 = tid >> 5;
#pragma unroll
        for (int q = 0; q < 4; q++) {
            int ci = ci8 + q * 8;
            smt[ci][ni] = x[((size_t)(b * 256 + c0 + ci)) * HW + n0 + ni];
        }
        __syncthreads();
        int cc = tid & 31, ni8 = tid >> 5;
#pragma unroll
        for (int q = 0; q < 4; q++) {
            int ni2 = ni8 + q * 8;
            ln[((size_t)((n0 + ni2) * 2 + b)) * 256 + c0 + cc] = smt[cc][ni2];
        }
    }
}

// ---------------- tf32 tensor GEMM with cp.async double buffering ----------------
// C[M,N] = A[M,256] @ W[N,256]^T + bias[N]; 64x64 tile, 256 threads (8 warps).
// Plain tf32 (round-to-nearest at fragment load), fp32 accumulate.
__device__ __forceinline__ void gemm_tc_body(const float* __restrict__ A, const float* __restrict__ Wm,
                                             const float* __restrict__ bias, float* __restrict__ C,
                                             int M, int N, int bm, int bn) {
    __shared__ __align__(16) float As[2][64][36];
    __shared__ __align__(16) float Bs[2][64][36];

    const int tid = threadIdx.x;
    const int w = tid >> 5, lane = tid & 31;
    const int r = lane >> 2, c = lane & 3;
    const int ms = (w & 3) * 16;     // m strip (16 rows)
    const int ns = (w >> 2) * 32;    // n half (4 subtiles of 8)

    const int row0 = tid >> 3;              // 0..31
    const int row1 = row0 + 32;             // 32..63
    const int k4   = (tid & 7) * 4;

    const float* gA0 = A + (size_t)((bm + row0 < M) ? bm + row0 : 0) * 256 + k4;
    const float* gA1 = A + (size_t)((bm + row1 < M) ? bm + row1 : 0) * 256 + k4;
    const int szA0 = (bm + row0 < M) ? 16 : 0;
    const int szA1 = (bm + row1 < M) ? 16 : 0;
    const float* gB0 = Wm + (size_t)(bn + row0) * 256 + k4;
    const float* gB1 = Wm + (size_t)(bn + row1) * 256 + k4;

    float acc[4][4];
#pragma unroll
    for (int nn = 0; nn < 4; nn++)
#pragma unroll
        for (int q = 0; q < 4; q++) acc[nn][q] = 0.f;

    // issue first chunk
    {
        unsigned sa0 = (unsigned)__cvta_generic_to_shared(&As[0][row0][k4]);
        unsigned sa1 = (unsigned)__cvta_generic_to_shared(&As[0][row1][k4]);
        unsigned sb0 = (unsigned)__cvta_generic_to_shared(&Bs[0][row0][k4]);
        unsigned sb1 = (unsigned)__cvta_generic_to_shared(&Bs[0][row1][k4]);
        cp_async16(sa0, gA0, szA0);
        cp_async16(sa1, gA1, szA1);
        cp_async16(sb0, gB0, 16);
        cp_async16(sb1, gB1, 16);
        CP_COMMIT();
    }

#pragma unroll
    for (int it = 0; it < 8; it++) {
        const int p = it & 1;
        if (it < 7) {
            const int knext = (it + 1) * 32;
            unsigned sa0 = (unsigned)__cvta_generic_to_shared(&As[p ^ 1][row0][k4]);
            unsigned sa1 = (unsigned)__cvta_generic_to_shared(&As[p ^ 1][row1][k4]);
            unsigned sb0 = (unsigned)__cvta_generic_to_shared(&Bs[p ^ 1][row0][k4]);
            unsigned sb1 = (unsigned)__cvta_generic_to_shared(&Bs[p ^ 1][row1][k4]);
            cp_async16(sa0, gA0 + knext, szA0);
            cp_async16(sa1, gA1 + knext, szA1);
            cp_async16(sb0, gB0 + knext, 16);
            cp_async16(sb1, gB1 + knext, 16);
            CP_COMMIT();
            CP_WAIT1();
        } else {
            CP_WAIT0();
        }
        __syncthreads();

#pragma unroll
        for (int kk = 0; kk < 32; kk += 8) {
            unsigned a0 = tf32u(As[p][ms + r][kk + c]);
            unsigned a1 = tf32u(As[p][ms + r + 8][kk + c]);
            unsigned a2 = tf32u(As[p][ms + r][kk + c + 4]);
            unsigned a3 = tf32u(As[p][ms + r + 8][kk + c + 4]);
#pragma unroll
            for (int nn = 0; nn < 4; nn++) {
                int n = ns + nn * 8 + r;
                unsigned b0 = tf32u(Bs[p][n][kk + c]);
                unsigned b1 = tf32u(Bs[p][n][kk + c + 4]);
                mma_tf32(acc[nn], a0, a1, a2, a3, b0, b1);
            }
        }
        __syncthreads();
    }

    // epilogue
#pragma unroll
    for (int nn = 0; nn < 4; nn++) {
        int ncol = bn + ns + nn * 8 + 2 * c;
        float2 bb = *(const float2*)(bias + ncol);
        int row = bm + ms + r;
        if (row < M)
            *(float2*)(C + (size_t)row * N + ncol) = make_float2(acc[nn][0] + bb.x, acc[nn][1] + bb.y);
        if (row + 8 < M)
            *(float2*)(C + (size_t)(row + 8) * N + ncol) = make_float2(acc[nn][2] + bb.x, acc[nn][3] + bb.y);
    }
}

__global__ __launch_bounds__(256)
void gemm_bias_kernel(const float* __restrict__ A, const float* __restrict__ W,
                      const float* __restrict__ bias, float* __restrict__ C, int M, int N) {
    gemm_tc_body(A, W, bias, C, M, N, blockIdx.y * 64, blockIdx.x * 64);
}

// dual GEMM: y < ySplit -> set0, else set1 (blocks with bn >= N early-exit)
__global__ __launch_bounds__(256)
void gemm_dual_kernel(const float* A0, const float* W0, const float* B0, float* C0, int M0, int N0,
                      const float* A1, const float* W1, const float* B1, float* C1, int M1, int N1,
                      int ySplit) {
    const float* A; const float* Wm; const float* bias; float* C; int M, N, by;
    if ((int)blockIdx.y < ySplit) { A = A0; Wm = W0; bias = B0; C = C0; M = M0; N = N0; by = blockIdx.y; }
    else { A = A1; Wm = W1; bias = B1; C = C1; M = M1; N = N1; by = blockIdx.y - ySplit; }
    int bn = blockIdx.x * 64;
    if (bn >= N) return;
    gemm_tc_body(A, Wm, bias, C, M, N, by * 64, bn);
}

// ---------------- tf32 MMA GAT attention (with K/V register prefetch) ----------------
// a0[i,j] = sigmoid(scale*(q0_i.k0_j - q1_i.k1_j));  O0 = A0@V0 ; O1 = (1-A0)@V1 (masked)
__global__ __launch_bounds__(256)
void gat_attn_mma(const float* __restrict__ qkvL, float* __restrict__ outL,
                  const float* __restrict__ qkvG, float* __restrict__ outG) {
    extern __shared__ float sm[];
    float* Qs = sm;                    // [64][68]  Qcat row-major [i][ck]
    float* Ks = sm + 64 * 68;          // [64][68]  Kcat row-major [j][ck] (b=1 negated)
    float* Am = sm + 2 * 64 * 68;      // [64][68]  a0 [i][j]
    float* Vs = sm + 3 * 64 * 68;      // [64][76]  V [j][ck]

    const float* qkv; float* out; int N, i0;
    if (blockIdx.x < 25) { qkv = qkvL; out = outL; N = NL; i0 = blockIdx.x * 64; }
    else                 { qkv = qkvG; out = outG; N = NG; i0 = (blockIdx.x - 25) * 64; }
    const int hc = blockIdx.y * 32;
    const int tid = threadIdx.x;
    const int w = tid >> 5, lane = tid & 31;
    const int r = lane >> 2, c = lane & 3;
    const float scale = 0.17677669529663687f;  // 1/sqrt(32)

    const int ljj = tid & 63;                 // j row
    const int ldq = tid >> 6;                 // 0..3
    // load Q tile (tf32-rounded)
#pragma unroll
    for (int t = 0; t < 4; t++) {
        int idx = tid + t * 256;
        int ii = idx & 63, dq = idx >> 6;
        int b = dq >> 3, d4 = (dq & 7) * 4;
        float4 v = make_float4(0.f, 0.f, 0.f, 0.f);
        if (i0 + ii < N) v = *(const float4*)(qkv + (size_t)((i0 + ii) * 2 + b) * 768 + hc + d4);
        float* dst = Qs + ii * 68 + b * 32 + d4;
        dst[0] = tf32r(v.x); dst[1] = tf32r(v.y); dst[2] = tf32r(v.z); dst[3] = tf32r(v.w);
    }

    const int ib = (w & 3) * 16;
    const int jb = (w >> 2) * 32;    // GEMM1 j half
    const int batch = w >> 2;        // GEMM2 batch / d half
    float o[4][4];
#pragma unroll
    for (int dn = 0; dn < 4; dn++)
#pragma unroll
        for (int q = 0; q < 4; q++) o[dn][q] = 0.f;

    // prefetch tile 0 into registers
    float4 pk[4], pv[4];
#pragma unroll
    for (int t = 0; t < 4; t++) {
        int dq = ldq + t * 4;
        int b = dq >> 3, d4 = (dq & 7) * 4;
        pk[t] = make_float4(0.f, 0.f, 0.f, 0.f);
        pv[t] = make_float4(0.f, 0.f, 0.f, 0.f);
        if (ljj < N) {
            const float* base = qkv + (size_t)(ljj * 2 + b) * 768 + hc;
            pk[t] = *(const float4*)(base + 256 + d4);
            pv[t] = *(const float4*)(base + 512 + d4);
        }
    }

    for (int j0 = 0; j0 < N; j0 += 64) {
        __syncthreads();
#pragma unroll
        for (int t = 0; t < 4; t++) {
            int dq = ldq + t * 4;
            int b = dq >> 3, d4 = (dq & 7) * 4;
            float4 kv = pk[t], vv = pv[t];
            if (b) { kv.x = -kv.x; kv.y = -kv.y; kv.z = -kv.z; kv.w = -kv.w; }
            int ck = b * 32 + d4;
            float* dk = Ks + ljj * 68 + ck;
            dk[0] = tf32r(kv.x); dk[1] = tf32r(kv.y); dk[2] = tf32r(kv.z); dk[3] = tf32r(kv.w);
            float* dv = Vs + ljj * 76 + ck;
            dv[0] = tf32r(vv.x); dv[1] = tf32r(vv.y); dv[2] = tf32r(vv.z); dv[3] = tf32r(vv.w);
        }
        __syncthreads();

        // GEMM1: S[16i x 32j] per warp, K-dim = 64 (concat)
        float s[4][4];
#pragma unroll
        for (int jn = 0; jn < 4; jn++)
#pragma unroll
            for (int q = 0; q < 4; q++) s[jn][q] = 0.f;
#pragma unroll
        for (int kk = 0; kk < 64; kk += 8) {
            unsigned a0 = f2u(Qs[(ib + r) * 68 + kk + c]);
            unsigned a1 = f2u(Qs[(ib + r + 8) * 68 + kk + c]);
            unsigned a2 = f2u(Qs[(ib + r) * 68 + kk + 4 + c]);
            unsigned a3 = f2u(Qs[(ib + r + 8) * 68 + kk + 4 + c]);
#pragma unroll
            for (int jn = 0; jn < 4; jn++) {
                const float* kb = Ks + (jb + jn * 8 + r) * 68 + kk;
                mma_tf32(s[jn], a0, a1, a2, a3, f2u(kb[c]), f2u(kb[4 + c]));
            }
        }
        // sigmoid + validity mask -> Am (tf32)
#pragma unroll
        for (int jn = 0; jn < 4; jn++) {
            int jc = jb + jn * 8 + 2 * c;
            bool valid = (j0 + jc) < N;   // pair-uniform (N even)
            float a00 = valid ? 1.f / (1.f + __expf(-scale * s[jn][0])) : 0.f;
            float a01 = valid ? 1.f / (1.f + __expf(-scale * s[jn][1])) : 0.f;
            float a10 = valid ? 1.f / (1.f + __expf(-scale * s[jn][2])) : 0.f;
            float a11 = valid ? 1.f / (1.f + __expf(-scale * s[jn][3])) : 0.f;
            *(float2*)(Am + (ib + r) * 68 + jc)     = make_float2(tf32r(a00), tf32r(a01));
            *(float2*)(Am + (ib + r + 8) * 68 + jc) = make_float2(tf32r(a10), tf32r(a11));
        }
        __syncthreads();

        // prefetch next tile during GEMM2
        if (j0 + 64 < N) {
#pragma unroll
            for (int t = 0; t < 4; t++) {
                int dq = ldq + t * 4;
                int b = dq >> 3, d4 = (dq & 7) * 4;
                int jj = j0 + 64 + ljj;
                pk[t] = make_float4(0.f, 0.f, 0.f, 0.f);
                pv[t] = make_float4(0.f, 0.f, 0.f, 0.f);
                if (jj < N) {
                    const float* base = qkv + (size_t)(jj * 2 + b) * 768 + hc;
                    pk[t] = *(const float4*)(base + 256 + d4);
                    pv[t] = *(const float4*)(base + 512 + d4);
                }
            }
        }

        // GEMM2: O[16i x 32d] per warp; batch0 uses A, batch1 uses (1-A) masked
#pragma unroll
        for (int kk = 0; kk < 64; kk += 8) {
            float f0 = Am[(ib + r) * 68 + kk + c];
            float f1 = Am[(ib + r + 8) * 68 + kk + c];
            float f2 = Am[(ib + r) * 68 + kk + 4 + c];
            float f3 = Am[(ib + r + 8) * 68 + kk + 4 + c];
            if (batch) {
                bool v0 = (j0 + kk + c) < N;
                bool v1 = (j0 + kk + 4 + c) < N;
                f0 = v0 ? tf32r(1.f - f0) : 0.f;
                f1 = v0 ? tf32r(1.f - f1) : 0.f;
                f2 = v1 ? tf32r(1.f - f2) : 0.f;
                f3 = v1 ? tf32r(1.f - f3) : 0.f;
            }
            unsigned a0 = f2u(f0), a1 = f2u(f1), a2 = f2u(f2), a3 = f2u(f3);
#pragma unroll
            for (int dn = 0; dn < 4; dn++) {
                int d = batch * 32 + dn * 8 + r;
                mma_tf32(o[dn], a0, a1, a2, a3,
                         f2u(Vs[(kk + c) * 76 + d]), f2u(Vs[(kk + 4 + c) * 76 + d]));
            }
        }
    }

    // epilogue: write O strip
#pragma unroll
    for (int dn = 0; dn < 4; dn++) {
        int d = dn * 8 + 2 * c;
        int i = i0 + ib + r;
        if (i < N)
            *(float2*)(out + (size_t)(i * 2 + batch) * 256 + hc + d) = make_float2(o[dn][0], o[dn][1]);
        if (i + 8 < N)
            *(float2*)(out + (size_t)((i + 8) * 2 + batch) * 256 + hc + d) = make_float2(o[dn][2], o[dn][3]);
    }
}

// ---------------- residual add + LayerNorm, warp-per-row, dual ----------------
__global__ __launch_bounds__(256)
void add_ln_dual(const float* __restrict__ yL, const float* __restrict__ resL,
                 const float* __restrict__ yG, const float* __restrict__ resG,
                 const float* __restrict__ ln_g, const float* __restrict__ ln_b,
                 float* __restrict__ outL, float* __restrict__ outG) {
    int w = threadIdx.x >> 5, lane = threadIdx.x & 31;
    int row = blockIdx.x * 8 + w;
    const float* y; const float* res; const float* g; const float* bt; float* out; int rr;
    if (row < ML) { y = yL; res = resL; g = ln_g + 256; bt = ln_b + 256; out = outL; rr = row; }
    else if (row < ML + MG) { y = yG; res = resG; g = ln_g; bt = ln_b; out = outG; rr = row - ML; }
    else return;

    float v[8];
    float s = 0.f, s2 = 0.f;
#pragma unroll
    for (int q = 0; q < 8; q++) {
        int c = q * 32 + lane;
        float t = y[(size_t)rr * 256 + c] + res[(size_t)rr * 256 + c];
        v[q] = t; s += t; s2 += t * t;
    }
#pragma unroll
    for (int o = 16; o; o >>= 1) {
        s  += __shfl_xor_sync(0xffffffffu, s,  o);
        s2 += __shfl_xor_sync(0xffffffffu, s2, o);
    }
    float mean = s * (1.f / 256.f);
    float var  = s2 * (1.f / 256.f) - mean * mean;
    float rs = rsqrtf(var + 1e-5f);
#pragma unroll
    for (int q = 0; q < 8; q++) {
        int c = q * 32 + lane;
        out[(size_t)rr * 256 + c] = (v[q] - mean) * rs * g[c] + bt[c];
    }
}

// ---------------- final: residual add + LN + transpose to [B,C,HW] ----------------
__global__ __launch_bounds__(512)
void add_ln_tr_kernel(const float* __restrict__ y, const float* __restrict__ res,
                      const float* __restrict__ g, const float* __restrict__ bt,
                      float* __restrict__ out) {
    __shared__ float smn[16][260];
    int w = threadIdx.x >> 5, lane = threadIdx.x & 31;
    int row = blockIdx.x * 16 + w;
    float v[8];
    float s = 0.f, s2 = 0.f;
#pragma unroll
    for (int q = 0; q < 8; q++) {
        float t = y[(size_t)row * 256 + q * 32 + lane] + res[(size_t)row * 256 + q * 32 + lane];
        v[q] = t; s += t; s2 += t * t;
    }
#pragma unroll
    for (int o = 16; o; o >>= 1) {
        s  += __shfl_xor_sync(0xffffffffu, s,  o);
        s2 += __shfl_xor_sync(0xffffffffu, s2, o);
    }
    float mean = s * (1.f / 256.f);
    float var  = s2 * (1.f / 256.f) - mean * mean;
    float rs = rsqrtf(var + 1e-5f);
#pragma unroll
    for (int q = 0; q < 8; q++) {
        int c = q * 32 + lane;
        smn[w][c] = (v[q] - mean) * rs * g[c] + bt[c];
    }
    __syncthreads();
    int n0 = blockIdx.x * 8;
    int p = threadIdx.x;
    int b = p >> 8, c = p & 255;
    float4 w0, w1;
    w0.x = smn[0 + b][c]; w0.y = smn[2 + b][c]; w0.z = smn[4 + b][c]; w0.w = smn[6 + b][c];
    w1.x = smn[8 + b][c]; w1.y = smn[10 + b][c]; w1.z = smn[12 + b][c]; w1.w = smn[14 + b][c];
    size_t off = ((size_t)b * 256 + c) * (size_t)HW + n0;
    *(float4*)(out + off)     = w0;
    *(float4*)(out + off + 4) = w1;
}

// ---------------- cross attention: Q[3200 rows], K/V from 100 distinct g_out rows ----------------
__global__ void cross_attn_kernel(const float* __restrict__ Q, const float* __restrict__ KV,
                                  float* __restrict__ out) {
    __shared__ float Kt[2][32][100];
    __shared__ float Vs[2][100][32];
    const int hc = blockIdx.y * 32;
    const int i0 = blockIdx.x * 100;
    const int tid = threadIdx.x;

    for (int idx = tid; idx < 2 * 32 * 100; idx += 256) {
        int j = idx % 100; int t = idx / 100; int d = t & 31; int b = t >> 5;
        Kt[b][d][j] = KV[(size_t)(j * 2 + b) * 512 + hc + d];
    }
    for (int idx = tid; idx < 2 * 100 * 32; idx += 256) {
        int d = idx & 31; int t = idx >> 5; int j = t % 100; int b = t / 100;
        Vs[b][j][d] = KV[(size_t)(j * 2 + b) * 512 + 256 + hc + d];
    }
    __syncthreads();

    const int w = tid >> 5, lane = tid & 31;
    const float scale = 0.17677669529663687f;

    for (int p = w; p < 200; p += 8) {
        int li = p >> 1, b = p & 1;
        int i = i0 + li;
        float q = Q[(size_t)(i * 2 + b) * 256 + hc + lane];
        float s0 = 0.f, s1 = 0.f, s2 = 0.f, s3 = 0.f;
#pragma unroll
        for (int d = 0; d < 32; d++) {
            float qd = __shfl_sync(0xffffffffu, q, d);
            s0 += qd * Kt[b][d][lane];
            s1 += qd * Kt[b][d][lane + 32];
            s2 += qd * Kt[b][d][lane + 64];
            if (lane < 4) s3 += qd * Kt[b][d][lane + 96];
        }
        s0 *= scale; s1 *= scale; s2 *= scale;
        s3 = (lane < 4) ? s3 * scale : -1e30f;
        float m = fmaxf(fmaxf(s0, s1), fmaxf(s2, s3));
#pragma unroll
        for (int o = 16; o; o >>= 1) m = fmaxf(m, __shfl_xor_sync(0xffffffffu, m, o));
        float e0 = __expf(s0 - m), e1 = __expf(s1 - m), e2 = __expf(s2 - m);
        float e3 = (lane < 4) ? __expf(s3 - m) : 0.f;
        float sum = e0 + e1 + e2 + e3;
#pragma unroll
        for (int o = 16; o; o >>= 1) sum += __shfl_xor_sync(0xffffffffu, sum, o);
        float inv = 1.0f / sum;
        float a0 = e0 * inv, a1 = e1 * inv, a2 = e2 * inv, a3 = e3 * inv;

        float oa = 0.f;
#pragma unroll
        for (int jj = 0; jj < 32; jj++) {
            float a = __shfl_sync(0xffffffffu, a0, jj);
            oa += a * Vs[b][jj][lane];
        }
#pragma unroll
        for (int jj = 0; jj < 32; jj++) {
            float a = __shfl_sync(0xffffffffu, a1, jj);
            oa += a * Vs[b][32 + jj][lane];
        }
#pragma unroll
        for (int jj = 0; jj < 32; jj++) {
            float a = __shfl_sync(0xffffffffu, a2, jj);
            oa += a * Vs[b][64 + jj][lane];
        }
#pragma unroll
        for (int jj = 0; jj < 4; jj++) {
            float a = __shfl_sync(0xffffffffu, a3, jj);
            oa += a * Vs[b][96 + jj][lane];
        }
        out[(size_t)(i * 2 + b) * 256 + hc + lane] = oa;
    }
}

// ---------------- launch ----------------
extern "C" void kernel_launch(void* const* d_in, const int* in_sizes, int n_in,
                              void* d_out, int out_size) {
    const float* x       = (const float*)d_in[0];
    const float* gat_W   = (const float*)d_in[1];   // [2][4][256][256]
    const float* gat_b   = (const float*)d_in[2];   // [2][4][256]
    // d_in[3] = gat_rel: edge bias constant along batch softmax axis -> cancels exactly
    const float* cross_W = (const float*)d_in[4];
    const float* cross_b = (const float*)d_in[5];
    const float* ln_g    = (const float*)d_in[6];
    const float* ln_b    = (const float*)d_in[7];
    float* out = (float*)d_out;

    float *Gn, *Ln, *qkvg, *qkvl, *att, *attg, *proj, *projg, *gout, *lout, *qc, *kvc, *catt, *cprj;
    cudaGetSymbolAddress((void**)&Gn,    d_Gn);
    cudaGetSymbolAddress((void**)&Ln,    d_Ln);
    cudaGetSymbolAddress((void**)&qkvg,  d_qkvg);
    cudaGetSymbolAddress((void**)&qkvl,  d_qkvl);
    cudaGetSymbolAddress((void**)&att,   d_att);
    cudaGetSymbolAddress((void**)&attg,  d_attg);
    cudaGetSymbolAddress((void**)&proj,  d_proj);
    cudaGetSymbolAddress((void**)&projg, d_projg);
    cudaGetSymbolAddress((void**)&gout,  d_gout);
    cudaGetSymbolAddress((void**)&lout,  d_lout);
    cudaGetSymbolAddress((void**)&qc,    d_qc);
    cudaGetSymbolAddress((void**)&kvc,   d_kvc);
    cudaGetSymbolAddress((void**)&catt,  d_catt);
    cudaGetSymbolAddress((void**)&cprj,  d_cprj);

    const int W2 = 256 * 256;
    const int ATTN_SMEM = (3 * 64 * 68 + 64 * 76) * 4;   // 71680 bytes
    cudaFuncSetAttribute(gat_attn_mma, cudaFuncAttributeMaxDynamicSharedMemorySize, ATTN_SMEM);

    // node construction (pool + coalesced transpose)
    prep_kernel<<<1000, 256>>>(x, Gn, Ln);

    // qkv projections (local + global merged), tf32 tensor GEMM
    gemm_dual_kernel<<<dim3(12, 54), 256>>>(
        Ln, gat_W + 4 * W2, gat_b + 1024, qkvl, ML, 768,
        Gn, gat_W,          gat_b,        qkvg, MG, 768, 50);

    // GAT attention (tf32 MMA, local x<25 + global x>=25)
    gat_attn_mma<<<dim3(27, HEADS), 256, ATTN_SMEM>>>(qkvl, att, qkvg, attg);

    // out projections (merged)
    gemm_dual_kernel<<<dim3(4, 54), 256>>>(
        att,  gat_W + 7 * W2, gat_b + 1024 + 768, proj,  ML, 256,
        attg, gat_W + 3 * W2, gat_b + 768,        projg, MG, 256, 50);

    // add + LN (merged, warp-per-row)
    add_ln_dual<<<(ML + MG) / 8, 256>>>(proj, Ln, projg, Gn, ln_g, ln_b, lout, gout);

    // cross projections: Q (local) + KV (global, 100 distinct keys) merged
    gemm_dual_kernel<<<dim3(8, 54), 256>>>(
        lout, cross_W,      cross_b,       qc,  ML, 256,
        gout, cross_W + W2, cross_b + 256, kvc, MG, 512, 50);

    cross_attn_kernel<<<dim3(16, HEADS), 256>>>(qc, kvc, catt);
    gemm_bias_kernel<<<dim3(4, 50), 256>>>(catt, cross_W + 3 * W2, cross_b + 768, cprj, ML, 256);
    add_ln_tr_kernel<<<200, 512>>>(cprj, lout, ln_g + 512, ln_b + 512, out);
}